// round 5
// baseline (speedup 1.0000x reference)
#include <cuda_runtime.h>

#define NPTS 131072
#define KNBR 27
#define FINC 3
#define FOUTC 32
#define EPSV 1e-5f

// static scratch (allocation rules forbid cudaMalloc)
__device__ float g_h[(size_t)NPTS * FOUTC];          // 16 MB intermediate h
__device__ float g_x4[(size_t)NPTS * 4];             // 2 MB padded x feats
__device__ int   g_idxT[(size_t)KNBR * NPTS];        // 14 MB transposed indices

typedef unsigned long long ull;

__device__ __forceinline__ ull pk2(float lo, float hi) {
    ull r; asm("mov.b64 %0, {%1, %2};" : "=l"(r) : "f"(lo), "f"(hi)); return r;
}
__device__ __forceinline__ void upk2(ull v, float& lo, float& hi) {
    asm("mov.b64 {%0, %1}, %2;" : "=f"(lo), "=f"(hi) : "l"(v));
}
__device__ __forceinline__ void ffma2(ull& d, ull a, ull b) {
    asm("fma.rn.f32x2 %0, %1, %2, %0;" : "+l"(d) : "l"(a), "l"(b));
}

// ---------------------------------------------------------------------------
// Pre-pass A: pack x_feats [N,3] -> g_x4 [N,4]
// ---------------------------------------------------------------------------
__global__ void __launch_bounds__(256) pack_x_kernel(const float* __restrict__ x)
{
    int n = blockIdx.x * 256 + threadIdx.x;
    if (n < NPTS) {
        float4 v;
        v.x = x[(size_t)n * 3 + 0];
        v.y = x[(size_t)n * 3 + 1];
        v.z = x[(size_t)n * 3 + 2];
        v.w = 0.f;
        ((float4*)g_x4)[n] = v;
    }
}

// ---------------------------------------------------------------------------
// Pre-pass B: transpose nbr_idx [N,K] -> g_idxT [K,N]  (smem-tiled)
// ---------------------------------------------------------------------------
__global__ void __launch_bounds__(256) transpose_idx_kernel(const int* __restrict__ nbr)
{
    __shared__ int sI[256 * KNBR];
    const int tid  = threadIdx.x;
    const int base = blockIdx.x * 256;
    for (int i = tid; i < 256 * KNBR; i += 256)
        sI[i] = nbr[(size_t)base * KNBR + i];
    __syncthreads();
#pragma unroll
    for (int k = 0; k < KNBR; k++)
        g_idxT[(size_t)k * NPTS + base + tid] = sI[tid * KNBR + k];
}

// ---------------------------------------------------------------------------
// Stage 1: h[n,o] = silu(bn( sum_{k,f} x4[idxT[k][n]].f * w1[k,f,o] ))
// thread-per-point, out-pairs packed f32x2
// ---------------------------------------------------------------------------
#define A_THREADS 256

__global__ void __launch_bounds__(A_THREADS) stage1_kernel(
    const float* __restrict__ w1,
    const float* __restrict__ g1,
    const float* __restrict__ b1,
    const float* __restrict__ m1,
    const float* __restrict__ v1)
{
    __shared__ float w1s[KNBR * FINC * FOUTC];
    __shared__ float sScale[FOUTC], sShift[FOUTC];

    const int tid = threadIdx.x;
    const int n   = blockIdx.x * A_THREADS + tid;

    for (int i = tid; i < KNBR * FINC * FOUTC; i += A_THREADS) w1s[i] = w1[i];
    if (tid < FOUTC) {
        float s = rsqrtf(v1[tid] + EPSV) * g1[tid];
        sScale[tid] = s;
        sShift[tid] = b1[tid] - m1[tid] * s;
    }
    __syncthreads();

    ull acc[16];   // out-pairs (o, o+1)
#pragma unroll
    for (int q = 0; q < 16; q++) acc[q] = 0ULL;

    for (int k = 0; k < KNBR; k++) {
        int idx = __ldg(g_idxT + (size_t)k * NPTS + n);
        float4 xv = __ldg((const float4*)g_x4 + idx);
        ull px0 = pk2(xv.x, xv.x);
        ull px1 = pk2(xv.y, xv.y);
        ull px2 = pk2(xv.z, xv.z);
        const ull* w0p = (const ull*)&w1s[(k * 3 + 0) * FOUTC];
        const ull* w1p = (const ull*)&w1s[(k * 3 + 1) * FOUTC];
        const ull* w2p = (const ull*)&w1s[(k * 3 + 2) * FOUTC];
#pragma unroll
        for (int q = 0; q < 16; q++) {
            ffma2(acc[q], px0, w0p[q]);
            ffma2(acc[q], px1, w1p[q]);
            ffma2(acc[q], px2, w2p[q]);
        }
    }

    float4* hp = (float4*)(g_h + (size_t)n * FOUTC);
#pragma unroll
    for (int o4 = 0; o4 < 8; o4++) {
        float r[4];
#pragma unroll
        for (int j = 0; j < 2; j++) {
            float lo, hi;
            upk2(acc[o4 * 2 + j], lo, hi);
            r[j * 2 + 0] = lo;
            r[j * 2 + 1] = hi;
        }
#pragma unroll
        for (int j = 0; j < 4; j++) {
            int o = o4 * 4 + j;
            float v = r[j] * sScale[o] + sShift[o];
            float sig = 1.f / (1.f + __expf(-v));
            r[j] = v * sig;
        }
        hp[o4] = make_float4(r[0], r[1], r[2], r[3]);
    }
}

// ---------------------------------------------------------------------------
// Stage 2: x_out[n,o] = sum_{k,f} h[idxT[k][n],f] * w2[k,f,o]; fuse point branch.
// 128 pts/block, 256 threads, thread tile 2 pts (f32x2-packed) x 8 outs.
// Double-buffered smem pipeline (gather k+1 overlaps math k), 1 sync/k.
// sA: ull layout [f][ (pt>>1) ^ (2*(f>>2)) ] -- XOR swizzle, conflict-free
//     for both gather STS (4 pts x 8 fc per warp) and math LDS.64.
// sB2: w2[k] pre-duplicated as f32x2 -> zero packing ALU in math loop.
// ---------------------------------------------------------------------------
#define B_THREADS 256
#define TILE_P    128

__global__ void __launch_bounds__(B_THREADS, 4) stage2_kernel(
    const float* __restrict__ z_feats,
    const float* __restrict__ w2,
    const float* __restrict__ mlp_w,
    const float* __restrict__ mlp_b,
    const float* __restrict__ mg,
    const float* __restrict__ mbt,
    const float* __restrict__ mm,
    const float* __restrict__ mv,
    float* __restrict__ out)
{
    __shared__ ull sA[2][FOUTC * 64];      // 2 x 16 KB   [f][pair swizzled]
    __shared__ ull sB2[2][FOUTC * FOUTC];  // 2 x 8 KB    [f][o] dup-packed

    const int tid  = threadIdx.x;
    const int og   = tid >> 6;       // 0..3 : outs [og*8, og*8+8)
    const int pr   = tid & 63;       // pair index: pts (2pr, 2pr+1)
    const int base = blockIdx.x * TILE_P;

    ull acc[8];
#pragma unroll
    for (int q = 0; q < 8; q++) acc[q] = 0ULL;

    // ---- gather stage k into buffer bs
    auto gather = [&](int k, int bs) {
        const int* __restrict__ idxk = g_idxT + (size_t)k * NPTS + base;
        float* A = (float*)sA[bs];
#pragma unroll
        for (int pass = 0; pass < 4; pass++) {
            int lin = pass * B_THREADS + tid;     // 0..1023
            int pt  = lin >> 3;                   // 0..127
            int fc  = lin & 7;                    // float4 chunk
            int idx = __ldg(idxk + pt);
            float4 v = __ldg((const float4*)(g_h + (size_t)idx * FOUTC) + fc);
            // ull-col swizzle: c = (pt>>1) ^ (2*fc); float addr = row*128 + c*2 + (pt&1)
            int c  = ((pt >> 1) ^ (fc << 1));
            int fo = (fc * 4) * 128 + c * 2 + (pt & 1);
            A[fo +   0] = v.x;
            A[fo + 128] = v.y;
            A[fo + 256] = v.z;
            A[fo + 384] = v.w;
        }
        float4 wv = __ldg((const float4*)(w2 + (size_t)k * FOUTC * FOUTC) + tid);
        ull* B = sB2[bs] + tid * 4;
        B[0] = pk2(wv.x, wv.x);
        B[1] = pk2(wv.y, wv.y);
        B[2] = pk2(wv.z, wv.z);
        B[3] = pk2(wv.w, wv.w);
    };

    gather(0, 0);

    for (int k = 0; k < KNBR; k++) {
        __syncthreads();                       // buf[k&1] ready; buf[(k+1)&1] free
        if (k + 1 < KNBR) gather(k + 1, (k + 1) & 1);

        const ull* Au = sA[k & 1];
        const ull* Bu = sB2[k & 1] + og * 8;
#pragma unroll
        for (int f = 0; f < FOUTC; f++) {
            ull a = Au[f * 64 + (pr ^ ((f >> 2) << 1))];
            const ull* bp = Bu + f * FOUTC;
            ffma2(acc[0], a, bp[0]); ffma2(acc[1], a, bp[1]);
            ffma2(acc[2], a, bp[2]); ffma2(acc[3], a, bp[3]);
            ffma2(acc[4], a, bp[4]); ffma2(acc[5], a, bp[5]);
            ffma2(acc[6], a, bp[6]); ffma2(acc[7], a, bp[7]);
        }
    }

    // ---- epilogue: point branch + fuse + duplicated write
    float zs[8], zsh[8], mw0[8], mw1[8], mw2[8], mbb[8];
#pragma unroll
    for (int q = 0; q < 8; q++) {
        int o = og * 8 + q;
        float s = rsqrtf(__ldg(mv + o) + EPSV) * __ldg(mg + o);
        zs[q]  = s;
        zsh[q] = __ldg(mbt + o) - __ldg(mm + o) * s;
        mw0[q] = __ldg(mlp_w + 0 * FOUTC + o);
        mw1[q] = __ldg(mlp_w + 1 * FOUTC + o);
        mw2[q] = __ldg(mlp_w + 2 * FOUTC + o);
        mbb[q] = __ldg(mlp_b + o);
    }

#pragma unroll
    for (int j = 0; j < 2; j++) {              // j: which point of the pair
        int n = base + pr * 2 + j;
        float z0 = __ldg(z_feats + (size_t)n * 3 + 0);
        float z1 = __ldg(z_feats + (size_t)n * 3 + 1);
        float z2 = __ldg(z_feats + (size_t)n * 3 + 2);
        float rv[8];
#pragma unroll
        for (int q = 0; q < 8; q++) {
            float lo, hi;
            upk2(acc[q], lo, hi);
            rv[q] = j ? hi : lo;
        }
#pragma unroll
        for (int q = 0; q < 8; q++) {
            float zv = z0 * mw0[q] + z1 * mw1[q] + z2 * mw2[q] + mbb[q];
            zv = zv * zs[q] + zsh[q];
            zv = fmaxf(zv, 0.f);
            rv[q] += zv;
        }
        float4 r0 = make_float4(rv[0], rv[1], rv[2], rv[3]);
        float4 r1 = make_float4(rv[4], rv[5], rv[6], rv[7]);
        float* p0 = out + (size_t)n * FOUTC + og * 8;
        float* p1 = p0 + (size_t)NPTS * FOUTC;
        ((float4*)p0)[0] = r0;
        ((float4*)p0)[1] = r1;
        ((float4*)p1)[0] = r0;
        ((float4*)p1)[1] = r1;
    }
}

// ---------------------------------------------------------------------------
extern "C" void kernel_launch(void* const* d_in, const int* in_sizes, int n_in,
                              void* d_out, int out_size)
{
    const float* x_feats   = (const float*)d_in[0];
    const float* z_feats   = (const float*)d_in[1];
    const int*   nbr_idx   = (const int*)  d_in[2];
    const float* w1        = (const float*)d_in[3];
    const float* bn1_gamma = (const float*)d_in[4];
    const float* bn1_beta  = (const float*)d_in[5];
    const float* bn1_mean  = (const float*)d_in[6];
    const float* bn1_var   = (const float*)d_in[7];
    const float* w2        = (const float*)d_in[8];
    const float* mlp_w     = (const float*)d_in[9];
    const float* mlp_b     = (const float*)d_in[10];
    const float* mlp_gamma = (const float*)d_in[11];
    const float* mlp_beta  = (const float*)d_in[12];
    const float* mlp_mean  = (const float*)d_in[13];
    const float* mlp_var   = (const float*)d_in[14];
    float* out = (float*)d_out;

    pack_x_kernel<<<(NPTS + 255) / 256, 256>>>(x_feats);
    transpose_idx_kernel<<<NPTS / 256, 256>>>(nbr_idx);

    stage1_kernel<<<NPTS / A_THREADS, A_THREADS>>>(
        w1, bn1_gamma, bn1_beta, bn1_mean, bn1_var);

    stage2_kernel<<<NPTS / TILE_P, B_THREADS>>>(
        z_feats, w2, mlp_w, mlp_b,
        mlp_gamma, mlp_beta, mlp_mean, mlp_var, out);
}

// round 6
// speedup vs baseline: 1.1032x; 1.1032x over previous
#include <cuda_runtime.h>

#define NPTS 131072
#define KNBR 27
#define FINC 3
#define FOUTC 32
#define EPSV 1e-5f

// static scratch (allocation rules forbid cudaMalloc)
__device__ float g_h[(size_t)NPTS * FOUTC];          // 16 MB intermediate h
__device__ float g_x4[(size_t)NPTS * 4];             // 2 MB padded x feats
__device__ float g_z4[(size_t)NPTS * 4];             // 2 MB padded z feats
__device__ int   g_idxT[(size_t)KNBR * NPTS];        // 14 MB transposed indices

typedef unsigned long long ull;

__device__ __forceinline__ ull pk2(float lo, float hi) {
    ull r; asm("mov.b64 %0, {%1, %2};" : "=l"(r) : "f"(lo), "f"(hi)); return r;
}
__device__ __forceinline__ void upk2(ull v, float& lo, float& hi) {
    asm("mov.b64 {%0, %1}, %2;" : "=f"(lo), "=f"(hi) : "l"(v));
}
__device__ __forceinline__ void ffma2(ull& d, ull a, ull b) {
    asm("fma.rn.f32x2 %0, %1, %2, %0;" : "+l"(d) : "l"(a), "l"(b));
}

// ---------------------------------------------------------------------------
// Pre-pass A: pack x_feats and z_feats [N,3] -> [N,4] float4
// ---------------------------------------------------------------------------
__global__ void __launch_bounds__(256) pack_xz_kernel(
    const float* __restrict__ x, const float* __restrict__ z)
{
    int n = blockIdx.x * 256 + threadIdx.x;
    if (n < NPTS) {
        float4 v;
        v.x = x[(size_t)n * 3 + 0];
        v.y = x[(size_t)n * 3 + 1];
        v.z = x[(size_t)n * 3 + 2];
        v.w = 0.f;
        ((float4*)g_x4)[n] = v;
        float4 w;
        w.x = z[(size_t)n * 3 + 0];
        w.y = z[(size_t)n * 3 + 1];
        w.z = z[(size_t)n * 3 + 2];
        w.w = 0.f;
        ((float4*)g_z4)[n] = w;
    }
}

// ---------------------------------------------------------------------------
// Pre-pass B: transpose nbr_idx [N,K] -> g_idxT [K,N]  (smem-tiled)
// ---------------------------------------------------------------------------
__global__ void __launch_bounds__(256) transpose_idx_kernel(const int* __restrict__ nbr)
{
    __shared__ int sI[256 * KNBR];
    const int tid  = threadIdx.x;
    const int base = blockIdx.x * 256;
    for (int i = tid; i < 256 * KNBR; i += 256)
        sI[i] = nbr[(size_t)base * KNBR + i];
    __syncthreads();
#pragma unroll
    for (int k = 0; k < KNBR; k++)
        g_idxT[(size_t)k * NPTS + base + tid] = sI[tid * KNBR + k];
}

// ---------------------------------------------------------------------------
// Stage 1: h[n,o] = silu(bn( sum_{k,f} x4[idxT[k][n]].f * w1[k,f,o] ))
// thread-per-point, out-pairs packed f32x2, w via broadcast LDS.128
// ---------------------------------------------------------------------------
#define A_THREADS 256

__global__ void __launch_bounds__(A_THREADS) stage1_kernel(
    const float* __restrict__ w1,
    const float* __restrict__ g1,
    const float* __restrict__ b1,
    const float* __restrict__ m1,
    const float* __restrict__ v1)
{
    __shared__ float w1s[KNBR * FINC * FOUTC];
    __shared__ float sScale[FOUTC], sShift[FOUTC];

    const int tid = threadIdx.x;
    const int n   = blockIdx.x * A_THREADS + tid;

    for (int i = tid; i < KNBR * FINC * FOUTC; i += A_THREADS) w1s[i] = w1[i];
    if (tid < FOUTC) {
        float s = rsqrtf(v1[tid] + EPSV) * g1[tid];
        sScale[tid] = s;
        sShift[tid] = b1[tid] - m1[tid] * s;
    }
    __syncthreads();

    ull acc[16];   // out-pairs (o, o+1)
#pragma unroll
    for (int q = 0; q < 16; q++) acc[q] = 0ULL;

    for (int k = 0; k < KNBR; k++) {
        int idx = __ldg(g_idxT + (size_t)k * NPTS + n);
        float4 xv = __ldg((const float4*)g_x4 + idx);
        ull px0 = pk2(xv.x, xv.x);
        ull px1 = pk2(xv.y, xv.y);
        ull px2 = pk2(xv.z, xv.z);
        const ulonglong2* w0p = (const ulonglong2*)&w1s[(k * 3 + 0) * FOUTC];
        const ulonglong2* w1p = (const ulonglong2*)&w1s[(k * 3 + 1) * FOUTC];
        const ulonglong2* w2p = (const ulonglong2*)&w1s[(k * 3 + 2) * FOUTC];
#pragma unroll
        for (int q = 0; q < 8; q++) {
            ulonglong2 a = w0p[q], b = w1p[q], c = w2p[q];
            ffma2(acc[q * 2 + 0], px0, a.x);
            ffma2(acc[q * 2 + 1], px0, a.y);
            ffma2(acc[q * 2 + 0], px1, b.x);
            ffma2(acc[q * 2 + 1], px1, b.y);
            ffma2(acc[q * 2 + 0], px2, c.x);
            ffma2(acc[q * 2 + 1], px2, c.y);
        }
    }

    float4* hp = (float4*)(g_h + (size_t)n * FOUTC);
#pragma unroll
    for (int o4 = 0; o4 < 8; o4++) {
        float r[4];
#pragma unroll
        for (int j = 0; j < 2; j++) {
            float lo, hi;
            upk2(acc[o4 * 2 + j], lo, hi);
            r[j * 2 + 0] = lo;
            r[j * 2 + 1] = hi;
        }
#pragma unroll
        for (int j = 0; j < 4; j++) {
            int o = o4 * 4 + j;
            float v = r[j] * sScale[o] + sShift[o];
            float sig = 1.f / (1.f + __expf(-v));
            r[j] = v * sig;
        }
        hp[o4] = make_float4(r[0], r[1], r[2], r[3]);
    }
}

// ---------------------------------------------------------------------------
// Stage 2: x_out[n,o] = sum_{k,f} h[idxT[k][n],f] * w2[k,f,o]; fuse point branch.
// 128 pts/block, 256 threads. Thread tile: 4 pts (2 f32x2 pairs) x 4 outs.
// Per f: 1 LDS.128 (a, both pairs) + 2 broadcast LDS.128 (b dup) + 8 FFMA2.
// sA: ull [f][pair ^ ((f>>2)<<2)] XOR swizzle -- conflict-free for the pair-
//     packed gather STS.64 AND the math LDS.128.
// Double-buffered (gather k+1 overlaps math k), 1 sync/k.
// ---------------------------------------------------------------------------
#define B_THREADS 256
#define TILE_P    128

__global__ void __launch_bounds__(B_THREADS, 3) stage2_kernel(
    const float* __restrict__ w2,
    const float* __restrict__ mlp_w,
    const float* __restrict__ mlp_b,
    const float* __restrict__ mg,
    const float* __restrict__ mbt,
    const float* __restrict__ mm,
    const float* __restrict__ mv,
    float* __restrict__ out)
{
    __shared__ ull sA[2][FOUTC * 64];      // 2 x 16 KB  [f][pair swizzled]
    __shared__ ull sB2[2][FOUTC * FOUTC];  // 2 x 8 KB   [f][o] dup-packed

    const int tid  = threadIdx.x;
    const int og   = tid >> 5;       // 0..7 : outs [og*4, og*4+4)
    const int pg   = tid & 31;       // pts 4pg..4pg+3 (pairs 2pg, 2pg+1)
    const int base = blockIdx.x * TILE_P;

    ull acc[2][4];   // [a-pair][out]
#pragma unroll
    for (int i = 0; i < 2; i++)
#pragma unroll
        for (int q = 0; q < 4; q++) acc[i][q] = 0ULL;

    // ---- gather stage k into buffer bs (pair-packed: 2 h-rows per item)
    auto gather = [&](int k, int bs) {
        const int2* __restrict__ idxk = (const int2*)(g_idxT + (size_t)k * NPTS + base);
#pragma unroll
        for (int pass = 0; pass < 2; pass++) {
            int lin  = pass * B_THREADS + tid;   // 0..511
            int pair = lin >> 3;                 // 0..63
            int fc   = lin & 7;                  // float4 chunk
            int2 ii  = __ldg(idxk + pair);
            float4 v0 = __ldg((const float4*)(g_h + (size_t)ii.x * FOUTC) + fc);
            float4 v1 = __ldg((const float4*)(g_h + (size_t)ii.y * FOUTC) + fc);
            int c = pair ^ (fc << 2);
            ull* A = sA[bs] + (fc * 4) * 64 + c;
            A[0]   = pk2(v0.x, v1.x);
            A[64]  = pk2(v0.y, v1.y);
            A[128] = pk2(v0.z, v1.z);
            A[192] = pk2(v0.w, v1.w);
        }
        float4 wv = __ldg((const float4*)(w2 + (size_t)k * FOUTC * FOUTC) + tid);
        ulonglong2* B = (ulonglong2*)(sB2[bs] + tid * 4);
        B[0] = make_ulonglong2(pk2(wv.x, wv.x), pk2(wv.y, wv.y));
        B[1] = make_ulonglong2(pk2(wv.z, wv.z), pk2(wv.w, wv.w));
    };

    gather(0, 0);

    for (int k = 0; k < KNBR; k++) {
        __syncthreads();                   // buf[k&1] ready; buf[(k+1)&1] free
        if (k + 1 < KNBR) gather(k + 1, (k + 1) & 1);

        const ull* Au = sA[k & 1];
        const ull* Bu = sB2[k & 1] + og * 4;
#pragma unroll
        for (int f = 0; f < FOUTC; f++) {
            int c0 = (2 * pg) ^ ((f >> 2) << 2);
            ulonglong2 a = *(const ulonglong2*)(Au + f * 64 + c0);
            const ulonglong2* bp = (const ulonglong2*)(Bu + f * FOUTC);
            ulonglong2 b0 = bp[0], b1 = bp[1];
            ffma2(acc[0][0], a.x, b0.x); ffma2(acc[0][1], a.x, b0.y);
            ffma2(acc[0][2], a.x, b1.x); ffma2(acc[0][3], a.x, b1.y);
            ffma2(acc[1][0], a.y, b0.x); ffma2(acc[1][1], a.y, b0.y);
            ffma2(acc[1][2], a.y, b1.x); ffma2(acc[1][3], a.y, b1.y);
        }
    }

    // ---- epilogue: point branch + fuse + duplicated write
    float zs[4], zsh[4], mw0[4], mw1[4], mw2[4], mbb[4];
#pragma unroll
    for (int q = 0; q < 4; q++) {
        int o = og * 4 + q;
        float s = rsqrtf(__ldg(mv + o) + EPSV) * __ldg(mg + o);
        zs[q]  = s;
        zsh[q] = __ldg(mbt + o) - __ldg(mm + o) * s;
        mw0[q] = __ldg(mlp_w + 0 * FOUTC + o);
        mw1[q] = __ldg(mlp_w + 1 * FOUTC + o);
        mw2[q] = __ldg(mlp_w + 2 * FOUTC + o);
        mbb[q] = __ldg(mlp_b + o);
    }

#pragma unroll
    for (int m = 0; m < 4; m++) {          // which of this thread's 4 points
        int n = base + 4 * pg + m;
        float4 z4 = __ldg((const float4*)g_z4 + n);
        int i = m >> 1;
        float rv[4];
#pragma unroll
        for (int q = 0; q < 4; q++) {
            float lo, hi;
            upk2(acc[i][q], lo, hi);
            rv[q] = (m & 1) ? hi : lo;
        }
#pragma unroll
        for (int q = 0; q < 4; q++) {
            float zv = z4.x * mw0[q] + z4.y * mw1[q] + z4.z * mw2[q] + mbb[q];
            zv = zv * zs[q] + zsh[q];
            zv = fmaxf(zv, 0.f);
            rv[q] += zv;
        }
        float4 r = make_float4(rv[0], rv[1], rv[2], rv[3]);
        float* p0 = out + (size_t)n * FOUTC + og * 4;
        *(float4*)p0 = r;
        *(float4*)(p0 + (size_t)NPTS * FOUTC) = r;
    }
}

// ---------------------------------------------------------------------------
extern "C" void kernel_launch(void* const* d_in, const int* in_sizes, int n_in,
                              void* d_out, int out_size)
{
    const float* x_feats   = (const float*)d_in[0];
    const float* z_feats   = (const float*)d_in[1];
    const int*   nbr_idx   = (const int*)  d_in[2];
    const float* w1        = (const float*)d_in[3];
    const float* bn1_gamma = (const float*)d_in[4];
    const float* bn1_beta  = (const float*)d_in[5];
    const float* bn1_mean  = (const float*)d_in[6];
    const float* bn1_var   = (const float*)d_in[7];
    const float* w2        = (const float*)d_in[8];
    const float* mlp_w     = (const float*)d_in[9];
    const float* mlp_b     = (const float*)d_in[10];
    const float* mlp_gamma = (const float*)d_in[11];
    const float* mlp_beta  = (const float*)d_in[12];
    const float* mlp_mean  = (const float*)d_in[13];
    const float* mlp_var   = (const float*)d_in[14];
    float* out = (float*)d_out;

    pack_xz_kernel<<<(NPTS + 255) / 256, 256>>>(x_feats, z_feats);
    transpose_idx_kernel<<<NPTS / 256, 256>>>(nbr_idx);

    stage1_kernel<<<NPTS / A_THREADS, A_THREADS>>>(
        w1, bn1_gamma, bn1_beta, bn1_mean, bn1_var);

    stage2_kernel<<<NPTS / TILE_P, B_THREADS>>>(
        w2, mlp_w, mlp_b,
        mlp_gamma, mlp_beta, mlp_mean, mlp_var, out);
}

// round 7
// speedup vs baseline: 1.1450x; 1.0380x over previous
#include <cuda_runtime.h>

#define NPTS 131072
#define KNBR 27
#define FINC 3
#define FOUTC 32
#define EPSV 1e-5f

// static scratch (allocation rules forbid cudaMalloc)
__device__ float g_h[(size_t)NPTS * FOUTC];          // 16 MB intermediate h
__device__ float g_x4[(size_t)NPTS * 4];             // 2 MB padded x feats
__device__ float g_z4[(size_t)NPTS * 4];             // 2 MB padded z feats
__device__ int   g_idxT[(size_t)KNBR * NPTS];        // 14 MB transposed indices

typedef unsigned long long ull;

__device__ __forceinline__ ull pk2(float lo, float hi) {
    ull r; asm("mov.b64 %0, {%1, %2};" : "=l"(r) : "f"(lo), "f"(hi)); return r;
}
__device__ __forceinline__ void upk2(ull v, float& lo, float& hi) {
    asm("mov.b64 {%0, %1}, %2;" : "=f"(lo), "=f"(hi) : "l"(v));
}
__device__ __forceinline__ void ffma2(ull& d, ull a, ull b) {
    asm("fma.rn.f32x2 %0, %1, %2, %0;" : "+l"(d) : "l"(a), "l"(b));
}

// ---------------------------------------------------------------------------
// Pre-pass A: pack x_feats and z_feats [N,3] -> [N,4] float4
// ---------------------------------------------------------------------------
__global__ void __launch_bounds__(256) pack_xz_kernel(
    const float* __restrict__ x, const float* __restrict__ z)
{
    int n = blockIdx.x * 256 + threadIdx.x;
    if (n < NPTS) {
        float4 v;
        v.x = x[(size_t)n * 3 + 0];
        v.y = x[(size_t)n * 3 + 1];
        v.z = x[(size_t)n * 3 + 2];
        v.w = 0.f;
        ((float4*)g_x4)[n] = v;
        float4 w;
        w.x = z[(size_t)n * 3 + 0];
        w.y = z[(size_t)n * 3 + 1];
        w.z = z[(size_t)n * 3 + 2];
        w.w = 0.f;
        ((float4*)g_z4)[n] = w;
    }
}

// ---------------------------------------------------------------------------
// Pre-pass B: transpose nbr_idx [N,K] -> g_idxT [K,N]  (smem-tiled)
// ---------------------------------------------------------------------------
__global__ void __launch_bounds__(256) transpose_idx_kernel(const int* __restrict__ nbr)
{
    __shared__ int sI[256 * KNBR];
    const int tid  = threadIdx.x;
    const int base = blockIdx.x * 256;
    for (int i = tid; i < 256 * KNBR; i += 256)
        sI[i] = nbr[(size_t)base * KNBR + i];
    __syncthreads();
#pragma unroll
    for (int k = 0; k < KNBR; k++)
        g_idxT[(size_t)k * NPTS + base + tid] = sI[tid * KNBR + k];
}

// ---------------------------------------------------------------------------
// Stage 1: h[n,o] = silu(bn( sum_{k,f} x4[idxT[k][n]].f * w1[k,f,o] ))
// thread-per-point, out-pairs packed f32x2, w via broadcast LDS.128
// ---------------------------------------------------------------------------
#define A_THREADS 256

__global__ void __launch_bounds__(A_THREADS) stage1_kernel(
    const float* __restrict__ w1,
    const float* __restrict__ g1,
    const float* __restrict__ b1,
    const float* __restrict__ m1,
    const float* __restrict__ v1)
{
    __shared__ float w1s[KNBR * FINC * FOUTC];
    __shared__ float sScale[FOUTC], sShift[FOUTC];

    const int tid = threadIdx.x;
    const int n   = blockIdx.x * A_THREADS + tid;

    for (int i = tid; i < KNBR * FINC * FOUTC; i += A_THREADS) w1s[i] = w1[i];
    if (tid < FOUTC) {
        float s = rsqrtf(v1[tid] + EPSV) * g1[tid];
        sScale[tid] = s;
        sShift[tid] = b1[tid] - m1[tid] * s;
    }
    __syncthreads();

    ull acc[16];   // out-pairs (o, o+1)
#pragma unroll
    for (int q = 0; q < 16; q++) acc[q] = 0ULL;

    for (int k = 0; k < KNBR; k++) {
        int idx = __ldg(g_idxT + (size_t)k * NPTS + n);
        float4 xv = __ldg((const float4*)g_x4 + idx);
        ull px0 = pk2(xv.x, xv.x);
        ull px1 = pk2(xv.y, xv.y);
        ull px2 = pk2(xv.z, xv.z);
        const ulonglong2* w0p = (const ulonglong2*)&w1s[(k * 3 + 0) * FOUTC];
        const ulonglong2* w1p = (const ulonglong2*)&w1s[(k * 3 + 1) * FOUTC];
        const ulonglong2* w2p = (const ulonglong2*)&w1s[(k * 3 + 2) * FOUTC];
#pragma unroll
        for (int q = 0; q < 8; q++) {
            ulonglong2 a = w0p[q], b = w1p[q], c = w2p[q];
            ffma2(acc[q * 2 + 0], px0, a.x);
            ffma2(acc[q * 2 + 1], px0, a.y);
            ffma2(acc[q * 2 + 0], px1, b.x);
            ffma2(acc[q * 2 + 1], px1, b.y);
            ffma2(acc[q * 2 + 0], px2, c.x);
            ffma2(acc[q * 2 + 1], px2, c.y);
        }
    }

    float4* hp = (float4*)(g_h + (size_t)n * FOUTC);
#pragma unroll
    for (int o4 = 0; o4 < 8; o4++) {
        float r[4];
#pragma unroll
        for (int j = 0; j < 2; j++) {
            float lo, hi;
            upk2(acc[o4 * 2 + j], lo, hi);
            r[j * 2 + 0] = lo;
            r[j * 2 + 1] = hi;
        }
#pragma unroll
        for (int j = 0; j < 4; j++) {
            int o = o4 * 4 + j;
            float v = r[j] * sScale[o] + sShift[o];
            float sig = 1.f / (1.f + __expf(-v));
            r[j] = v * sig;
        }
        hp[o4] = make_float4(r[0], r[1], r[2], r[3]);
    }
}

// ---------------------------------------------------------------------------
// Stage 2: x_out[n,o] = sum_{k,f} h[idxT[k][n],f] * w2[k,f,o]; fuse point branch.
// 128 pts/block, 256 threads. Thread tile: 4 pts (2 f32x2 pairs) x 4 outs.
// 2-D warp layout: lane = (o_lane 0..3)<<3 | (pt_lane 0..7)
//   warp covers 32 points x 16 outs ->
//   a-LDS.128 per f: 8 distinct 16B chunks, 4-way broadcast (128 B)
//   b-LDS.128 per f: 4 distinct dup-quads, 8-way broadcast   (128 B)
//   -> crossbar ~16 cyc per f per SM vs FMA ~32 cyc: FMA-bound.
// sA: ull [f][pair ^ ((f>>2)<<1)] swizzle: math LDS conflict-free,
//     gather STS.64 uniform 2-way (hidden). Double-buffered, 1 sync/k.
// ---------------------------------------------------------------------------
#define B_THREADS 256
#define TILE_P    128

__global__ void __launch_bounds__(B_THREADS, 3) stage2_kernel(
    const float* __restrict__ w2,
    const float* __restrict__ mlp_w,
    const float* __restrict__ mlp_b,
    const float* __restrict__ mg,
    const float* __restrict__ mbt,
    const float* __restrict__ mm,
    const float* __restrict__ mv,
    float* __restrict__ out)
{
    __shared__ ull sA[2][FOUTC * 64];      // 2 x 16 KB  [f][pair swizzled]
    __shared__ ull sB2[2][FOUTC * FOUTC];  // 2 x 8 KB   [f][o] dup-packed

    const int tid  = threadIdx.x;
    const int lane = tid & 31;
    const int w    = tid >> 5;
    // 2-D mapping: pair-group 0..31 (pairs 2pgi,2pgi+1), out-quad 0..7
    const int pgi  = ((w & 3) << 3) | (lane & 7);   // 0..31
    const int oq   = ((w >> 2) << 2) | (lane >> 3); // 0..7
    const int base = blockIdx.x * TILE_P;

    ull acc[2][4];   // [a-pair][out-pair]
#pragma unroll
    for (int i = 0; i < 2; i++)
#pragma unroll
        for (int q = 0; q < 4; q++) acc[i][q] = 0ULL;

    // ---- gather stage k into buffer bs (pair-packed: 2 h-rows per item)
    auto gather = [&](int k, int bs) {
        const int2* __restrict__ idxk = (const int2*)(g_idxT + (size_t)k * NPTS + base);
#pragma unroll
        for (int pass = 0; pass < 2; pass++) {
            int lin  = pass * B_THREADS + tid;   // 0..511
            int pair = lin >> 3;                 // 0..63
            int fc   = lin & 7;                  // float4 chunk
            int2 ii  = __ldg(idxk + pair);
            float4 v0 = __ldg((const float4*)(g_h + (size_t)ii.x * FOUTC) + fc);
            float4 v1 = __ldg((const float4*)(g_h + (size_t)ii.y * FOUTC) + fc);
            int c = pair ^ (fc << 1);
            ull* A = sA[bs] + (fc * 4) * 64 + c;
            A[0]   = pk2(v0.x, v1.x);
            A[64]  = pk2(v0.y, v1.y);
            A[128] = pk2(v0.z, v1.z);
            A[192] = pk2(v0.w, v1.w);
        }
        float4 wv = __ldg((const float4*)(w2 + (size_t)k * FOUTC * FOUTC) + tid);
        ulonglong2* B = (ulonglong2*)(sB2[bs] + tid * 4);
        B[0] = make_ulonglong2(pk2(wv.x, wv.x), pk2(wv.y, wv.y));
        B[1] = make_ulonglong2(pk2(wv.z, wv.z), pk2(wv.w, wv.w));
    };

    gather(0, 0);

    for (int k = 0; k < KNBR; k++) {
        __syncthreads();                   // buf[k&1] ready; buf[(k+1)&1] free
        if (k + 1 < KNBR) gather(k + 1, (k + 1) & 1);

        const ull* Au = sA[k & 1];
        const ull* Bu = sB2[k & 1] + oq * 4;
#pragma unroll
        for (int f = 0; f < FOUTC; f++) {
            int c0 = (2 * pgi) ^ ((f >> 2) << 1);
            ulonglong2 a = *(const ulonglong2*)(Au + f * 64 + c0);
            const ulonglong2* bp = (const ulonglong2*)(Bu + f * FOUTC);
            ulonglong2 b0 = bp[0], b1 = bp[1];
            ffma2(acc[0][0], a.x, b0.x); ffma2(acc[0][1], a.x, b0.y);
            ffma2(acc[0][2], a.x, b1.x); ffma2(acc[0][3], a.x, b1.y);
            ffma2(acc[1][0], a.y, b0.x); ffma2(acc[1][1], a.y, b0.y);
            ffma2(acc[1][2], a.y, b1.x); ffma2(acc[1][3], a.y, b1.y);
        }
    }

    // ---- epilogue: point branch + fuse + duplicated write
    float zs[4], zsh[4], mw0[4], mw1[4], mw2[4], mbb[4];
#pragma unroll
    for (int q = 0; q < 4; q++) {
        int o = oq * 4 + q;
        float s = rsqrtf(__ldg(mv + o) + EPSV) * __ldg(mg + o);
        zs[q]  = s;
        zsh[q] = __ldg(mbt + o) - __ldg(mm + o) * s;
        mw0[q] = __ldg(mlp_w + 0 * FOUTC + o);
        mw1[q] = __ldg(mlp_w + 1 * FOUTC + o);
        mw2[q] = __ldg(mlp_w + 2 * FOUTC + o);
        mbb[q] = __ldg(mlp_b + o);
    }

#pragma unroll
    for (int m = 0; m < 4; m++) {          // which of this thread's 4 points
        int n = base + 4 * pgi + m;
        float4 z4 = __ldg((const float4*)g_z4 + n);
        int i = m >> 1;
        float rv[4];
#pragma unroll
        for (int q = 0; q < 4; q++) {
            float lo, hi;
            upk2(acc[i][q], lo, hi);
            rv[q] = (m & 1) ? hi : lo;
        }
#pragma unroll
        for (int q = 0; q < 4; q++) {
            float zv = z4.x * mw0[q] + z4.y * mw1[q] + z4.z * mw2[q] + mbb[q];
            zv = zv * zs[q] + zsh[q];
            zv = fmaxf(zv, 0.f);
            rv[q] += zv;
        }
        float4 r = make_float4(rv[0], rv[1], rv[2], rv[3]);
        float* p0 = out + (size_t)n * FOUTC + oq * 4;
        *(float4*)p0 = r;
        *(float4*)(p0 + (size_t)NPTS * FOUTC) = r;
    }
}

// ---------------------------------------------------------------------------
extern "C" void kernel_launch(void* const* d_in, const int* in_sizes, int n_in,
                              void* d_out, int out_size)
{
    const float* x_feats   = (const float*)d_in[0];
    const float* z_feats   = (const float*)d_in[1];
    const int*   nbr_idx   = (const int*)  d_in[2];
    const float* w1        = (const float*)d_in[3];
    const float* bn1_gamma = (const float*)d_in[4];
    const float* bn1_beta  = (const float*)d_in[5];
    const float* bn1_mean  = (const float*)d_in[6];
    const float* bn1_var   = (const float*)d_in[7];
    const float* w2        = (const float*)d_in[8];
    const float* mlp_w     = (const float*)d_in[9];
    const float* mlp_b     = (const float*)d_in[10];
    const float* mlp_gamma = (const float*)d_in[11];
    const float* mlp_beta  = (const float*)d_in[12];
    const float* mlp_mean  = (const float*)d_in[13];
    const float* mlp_var   = (const float*)d_in[14];
    float* out = (float*)d_out;

    pack_xz_kernel<<<(NPTS + 255) / 256, 256>>>(x_feats, z_feats);
    transpose_idx_kernel<<<NPTS / 256, 256>>>(nbr_idx);

    stage1_kernel<<<NPTS / A_THREADS, A_THREADS>>>(
        w1, bn1_gamma, bn1_beta, bn1_mean, bn1_var);

    stage2_kernel<<<NPTS / TILE_P, B_THREADS>>>(
        w2, mlp_w, mlp_b,
        mlp_gamma, mlp_beta, mlp_mean, mlp_var, out);
}

// round 9
// speedup vs baseline: 1.3216x; 1.1542x over previous
#include <cuda_runtime.h>
#include <cuda_fp16.h>

#define NPTS 131072
#define KNBR 27
#define FINC 3
#define FOUTC 32
#define EPSV 1e-5f

// static scratch (allocation rules forbid cudaMalloc)
__device__ __align__(16) __half g_h16[(size_t)NPTS * FOUTC];  // 8 MB fp16 h
__device__ float g_x4[(size_t)NPTS * 4];                      // 2 MB padded x
__device__ float g_z4[(size_t)NPTS * 4];                      // 2 MB padded z
__device__ int   g_idxT[(size_t)KNBR * NPTS];                 // 14 MB idx^T

typedef unsigned long long ull;
typedef unsigned int uint;

__device__ __forceinline__ ull pk2(float lo, float hi) {
    ull r; asm("mov.b64 %0, {%1, %2};" : "=l"(r) : "f"(lo), "f"(hi)); return r;
}
__device__ __forceinline__ void upk2(ull v, float& lo, float& hi) {
    asm("mov.b64 {%0, %1}, %2;" : "=f"(lo), "=f"(hi) : "l"(v));
}
__device__ __forceinline__ void ffma2(ull& d, ull a, ull b) {
    asm("fma.rn.f32x2 %0, %1, %2, %0;" : "+l"(d) : "l"(a), "l"(b));
}
__device__ __forceinline__ uint prmt(uint a, uint b, uint sel) {
    uint r; asm("prmt.b32 %0, %1, %2, %3;" : "=r"(r) : "r"(a), "r"(b), "r"(sel));
    return r;
}

// ---------------------------------------------------------------------------
// Pre-pass A: pack x_feats and z_feats [N,3] -> [N,4] float4
// ---------------------------------------------------------------------------
__global__ void __launch_bounds__(256) pack_xz_kernel(
    const float* __restrict__ x, const float* __restrict__ z)
{
    int n = blockIdx.x * 256 + threadIdx.x;
    if (n < NPTS) {
        float4 v;
        v.x = x[(size_t)n * 3 + 0];
        v.y = x[(size_t)n * 3 + 1];
        v.z = x[(size_t)n * 3 + 2];
        v.w = 0.f;
        ((float4*)g_x4)[n] = v;
        float4 w;
        w.x = z[(size_t)n * 3 + 0];
        w.y = z[(size_t)n * 3 + 1];
        w.z = z[(size_t)n * 3 + 2];
        w.w = 0.f;
        ((float4*)g_z4)[n] = w;
    }
}

// ---------------------------------------------------------------------------
// Pre-pass B: transpose nbr_idx [N,K] -> g_idxT [K,N]
// ---------------------------------------------------------------------------
__global__ void __launch_bounds__(256) transpose_idx_kernel(const int* __restrict__ nbr)
{
    __shared__ int sI[256 * KNBR];
    const int tid  = threadIdx.x;
    const int base = blockIdx.x * 256;
    for (int i = tid; i < 256 * KNBR; i += 256)
        sI[i] = nbr[(size_t)base * KNBR + i];
    __syncthreads();
#pragma unroll
    for (int k = 0; k < KNBR; k++)
        g_idxT[(size_t)k * NPTS + base + tid] = sI[tid * KNBR + k];
}

// ---------------------------------------------------------------------------
// Stage 1: h = silu(bn(gather(x) @ w1)) -> fp16
// ---------------------------------------------------------------------------
#define A_THREADS 256

__global__ void __launch_bounds__(A_THREADS) stage1_kernel(
    const float* __restrict__ w1,
    const float* __restrict__ g1,
    const float* __restrict__ b1,
    const float* __restrict__ m1,
    const float* __restrict__ v1)
{
    __shared__ float w1s[KNBR * FINC * FOUTC];
    __shared__ float sScale[FOUTC], sShift[FOUTC];

    const int tid = threadIdx.x;
    const int n   = blockIdx.x * A_THREADS + tid;

    for (int i = tid; i < KNBR * FINC * FOUTC; i += A_THREADS) w1s[i] = w1[i];
    if (tid < FOUTC) {
        float s = rsqrtf(v1[tid] + EPSV) * g1[tid];
        sScale[tid] = s;
        sShift[tid] = b1[tid] - m1[tid] * s;
    }
    __syncthreads();

    ull acc[16];
#pragma unroll
    for (int q = 0; q < 16; q++) acc[q] = 0ULL;

    for (int k = 0; k < KNBR; k++) {
        int idx = __ldg(g_idxT + (size_t)k * NPTS + n);
        float4 xv = __ldg((const float4*)g_x4 + idx);
        ull px0 = pk2(xv.x, xv.x);
        ull px1 = pk2(xv.y, xv.y);
        ull px2 = pk2(xv.z, xv.z);
        const ulonglong2* w0p = (const ulonglong2*)&w1s[(k * 3 + 0) * FOUTC];
        const ulonglong2* w1p = (const ulonglong2*)&w1s[(k * 3 + 1) * FOUTC];
        const ulonglong2* w2p = (const ulonglong2*)&w1s[(k * 3 + 2) * FOUTC];
#pragma unroll
        for (int q = 0; q < 8; q++) {
            ulonglong2 a = w0p[q], b = w1p[q], c = w2p[q];
            ffma2(acc[q * 2 + 0], px0, a.x);
            ffma2(acc[q * 2 + 1], px0, a.y);
            ffma2(acc[q * 2 + 0], px1, b.x);
            ffma2(acc[q * 2 + 1], px1, b.y);
            ffma2(acc[q * 2 + 0], px2, c.x);
            ffma2(acc[q * 2 + 1], px2, c.y);
        }
    }

    // BN + SiLU, convert to fp16, store 64B row as 4x uint4
    uint4* hp = (uint4*)(g_h16 + (size_t)n * FOUTC);
#pragma unroll
    for (int c = 0; c < 4; c++) {          // chunk of 8 outs
        float r[8];
#pragma unroll
        for (int j = 0; j < 4; j++) {
            float lo, hi;
            upk2(acc[c * 4 + j], lo, hi);
            r[j * 2 + 0] = lo;
            r[j * 2 + 1] = hi;
        }
        uint w[4];
#pragma unroll
        for (int j = 0; j < 8; j++) {
            int o = c * 8 + j;
            float v = r[j] * sScale[o] + sShift[o];
            float sig = 1.f / (1.f + __expf(-v));
            r[j] = v * sig;
        }
#pragma unroll
        for (int j = 0; j < 4; j++) {
            __half2 h2 = __floats2half2_rn(r[j * 2], r[j * 2 + 1]);
            w[j] = *(uint*)&h2;
        }
        hp[c] = make_uint4(w[0], w[1], w[2], w[3]);
    }
}

// ---------------------------------------------------------------------------
// Stage 2: x_out = gather(h) @ w2 (+ fused point branch), h in fp16.
// TILE_P=256 pts, 128 threads. Thread tile: 8 pts x 8 outs (32 f32x2 acc).
// Per f per thread: 1 LDS.128 (4 half2 = 8 pts) + 2 LDS.128 (b, 8 fp32 outs)
//                   + cvt/pk2 ALU + 32 FFMA2  -> crossbar 12 cyc/warp/f vs
//                   FMA 64 SMSP-cyc: FMA-bound.
// sA (uint = half2): [f][pair ^ (fc<<3)], fc=f>>3. Conflict-free for gather
// STS.32 and math LDS.128 (verified). Double-buffered, 1 sync/k.
// ---------------------------------------------------------------------------
#define B_THREADS 128
#define TILE_P    256
#define NPAIR     128

__global__ void __launch_bounds__(B_THREADS, 5) stage2_kernel(
    const float* __restrict__ w2,
    const float* __restrict__ mlp_w,
    const float* __restrict__ mlp_b,
    const float* __restrict__ mg,
    const float* __restrict__ mbt,
    const float* __restrict__ mm,
    const float* __restrict__ mv,
    float* __restrict__ out)
{
    __shared__ uint  sAu[2][FOUTC * NPAIR];   // 2 x 16 KB  half2 tiles
    __shared__ float sBf[2][FOUTC * FOUTC];   // 2 x 4 KB   w2[k] natural

    const int tid  = threadIdx.x;
    const int lane = tid & 31;
    const int w    = tid >> 5;                 // warp 0..3
    const int pgt  = (w << 3) | (lane & 7);    // pair-group 0..31 (4 pairs)
    const int oq   = lane >> 3;                // out-octet 0..3 (8 outs)
    const int base = blockIdx.x * TILE_P;

    ull acc[4][8];   // [pair-in-group][out]
#pragma unroll
    for (int i = 0; i < 4; i++)
#pragma unroll
        for (int q = 0; q < 8; q++) acc[i][q] = 0ULL;

    // ---- gather stage k into buffer bs
    auto gather = [&](int k, int bs) {
        const int2* __restrict__ idxk = (const int2*)(g_idxT + (size_t)k * NPTS + base);
        uint* A = sAu[bs];
#pragma unroll
        for (int pass = 0; pass < 4; pass++) {
            int lin  = pass * B_THREADS + tid;   // 0..511
            int pair = lin >> 2;                 // 0..127
            int fc   = lin & 3;                  // 16B chunk (8 f)
            int2 ii  = __ldg(idxk + pair);
            uint4 v0 = __ldg((const uint4*)(g_h16 + (size_t)ii.x * FOUTC) + fc);
            uint4 v1 = __ldg((const uint4*)(g_h16 + (size_t)ii.y * FOUTC) + fc);
            int col = pair ^ (fc << 3);
            uint* Af = A + (fc * 8) * NPAIR + col;
            Af[0 * NPAIR] = prmt(v0.x, v1.x, 0x5410);
            Af[1 * NPAIR] = prmt(v0.x, v1.x, 0x7632);
            Af[2 * NPAIR] = prmt(v0.y, v1.y, 0x5410);
            Af[3 * NPAIR] = prmt(v0.y, v1.y, 0x7632);
            Af[4 * NPAIR] = prmt(v0.z, v1.z, 0x5410);
            Af[5 * NPAIR] = prmt(v0.z, v1.z, 0x7632);
            Af[6 * NPAIR] = prmt(v0.w, v1.w, 0x5410);
            Af[7 * NPAIR] = prmt(v0.w, v1.w, 0x7632);
        }
        // stage w2[k] natural fp32: 1024 floats, 128 threads x 2 float4
        const float4* wk = (const float4*)(w2 + (size_t)k * FOUTC * FOUTC);
        ((float4*)sBf[bs])[tid]       = __ldg(wk + tid);
        ((float4*)sBf[bs])[tid + 128] = __ldg(wk + tid + 128);
    };

    gather(0, 0);

    for (int k = 0; k < KNBR; k++) {
        __syncthreads();                   // buf[k&1] ready; buf[(k+1)&1] free
        if (k + 1 < KNBR) gather(k + 1, (k + 1) & 1);

        const uint*  Au = sAu[k & 1];
        const float* Bu = sBf[k & 1];
        for (int fc = 0; fc < 4; fc++) {            // outer: 16B chunk
            const uint* Ac = Au + (fc * 8) * NPAIR + (((4 * pgt) ^ (fc << 3)));
#pragma unroll
            for (int j = 0; j < 8; j++) {           // inner f within chunk
                int f = fc * 8 + j;
                uint4 av = *(const uint4*)(Ac + j * NPAIR);
                float2 a0 = __half22float2(*(__half2*)&av.x);
                float2 a1 = __half22float2(*(__half2*)&av.y);
                float2 a2 = __half22float2(*(__half2*)&av.z);
                float2 a3 = __half22float2(*(__half2*)&av.w);
                ull pa0 = pk2(a0.x, a0.y);
                ull pa1 = pk2(a1.x, a1.y);
                ull pa2 = pk2(a2.x, a2.y);
                ull pa3 = pk2(a3.x, a3.y);
                const float4* bp = (const float4*)(Bu + f * FOUTC + oq * 8);
                float4 b0 = bp[0], b1 = bp[1];
                ull bd0 = pk2(b0.x, b0.x), bd1 = pk2(b0.y, b0.y);
                ull bd2 = pk2(b0.z, b0.z), bd3 = pk2(b0.w, b0.w);
                ull bd4 = pk2(b1.x, b1.x), bd5 = pk2(b1.y, b1.y);
                ull bd6 = pk2(b1.z, b1.z), bd7 = pk2(b1.w, b1.w);
                ffma2(acc[0][0], pa0, bd0); ffma2(acc[0][1], pa0, bd1);
                ffma2(acc[0][2], pa0, bd2); ffma2(acc[0][3], pa0, bd3);
                ffma2(acc[0][4], pa0, bd4); ffma2(acc[0][5], pa0, bd5);
                ffma2(acc[0][6], pa0, bd6); ffma2(acc[0][7], pa0, bd7);
                ffma2(acc[1][0], pa1, bd0); ffma2(acc[1][1], pa1, bd1);
                ffma2(acc[1][2], pa1, bd2); ffma2(acc[1][3], pa1, bd3);
                ffma2(acc[1][4], pa1, bd4); ffma2(acc[1][5], pa1, bd5);
                ffma2(acc[1][6], pa1, bd6); ffma2(acc[1][7], pa1, bd7);
                ffma2(acc[2][0], pa2, bd0); ffma2(acc[2][1], pa2, bd1);
                ffma2(acc[2][2], pa2, bd2); ffma2(acc[2][3], pa2, bd3);
                ffma2(acc[2][4], pa2, bd4); ffma2(acc[2][5], pa2, bd5);
                ffma2(acc[2][6], pa2, bd6); ffma2(acc[2][7], pa2, bd7);
                ffma2(acc[3][0], pa3, bd0); ffma2(acc[3][1], pa3, bd1);
                ffma2(acc[3][2], pa3, bd2); ffma2(acc[3][3], pa3, bd3);
                ffma2(acc[3][4], pa3, bd4); ffma2(acc[3][5], pa3, bd5);
                ffma2(acc[3][6], pa3, bd6); ffma2(acc[3][7], pa3, bd7);
            }
        }
    }

    // ---- epilogue: point branch + fuse + duplicated write
    float zs[8], zsh[8], mw0[8], mw1[8], mw2[8], mbb[8];
#pragma unroll
    for (int q = 0; q < 8; q++) {
        int o = oq * 8 + q;
        float s = rsqrtf(__ldg(mv + o) + EPSV) * __ldg(mg + o);
        zs[q]  = s;
        zsh[q] = __ldg(mbt + o) - __ldg(mm + o) * s;
        mw0[q] = __ldg(mlp_w + 0 * FOUTC + o);
        mw1[q] = __ldg(mlp_w + 1 * FOUTC + o);
        mw2[q] = __ldg(mlp_w + 2 * FOUTC + o);
        mbb[q] = __ldg(mlp_b + o);
    }

#pragma unroll
    for (int pp = 0; pp < 4; pp++) {         // thread's 4 pairs
#pragma unroll
        for (int s = 0; s < 2; s++) {        // pt within pair (lo/hi)
            int n = base + (4 * pgt + pp) * 2 + s;
            float4 z4 = __ldg((const float4*)g_z4 + n);
            float rv[8];
#pragma unroll
            for (int q = 0; q < 8; q++) {
                float lo, hi;
                upk2(acc[pp][q], lo, hi);
                rv[q] = s ? hi : lo;
            }
#pragma unroll
            for (int q = 0; q < 8; q++) {
                float zv = z4.x * mw0[q] + z4.y * mw1[q] + z4.z * mw2[q] + mbb[q];
                zv = zv * zs[q] + zsh[q];
                zv = fmaxf(zv, 0.f);
                rv[q] += zv;
            }
            float4 r0 = make_float4(rv[0], rv[1], rv[2], rv[3]);
            float4 r1 = make_float4(rv[4], rv[5], rv[6], rv[7]);
            float* p0 = out + (size_t)n * FOUTC + oq * 8;
            float* p1 = p0 + (size_t)NPTS * FOUTC;
            ((float4*)p0)[0] = r0;
            ((float4*)p0)[1] = r1;
            ((float4*)p1)[0] = r0;
            ((float4*)p1)[1] = r1;
        }
    }
}

// ---------------------------------------------------------------------------
extern "C" void kernel_launch(void* const* d_in, const int* in_sizes, int n_in,
                              void* d_out, int out_size)
{
    const float* x_feats   = (const float*)d_in[0];
    const float* z_feats   = (const float*)d_in[1];
    const int*   nbr_idx   = (const int*)  d_in[2];
    const float* w1        = (const float*)d_in[3];
    const float* bn1_gamma = (const float*)d_in[4];
    const float* bn1_beta  = (const float*)d_in[5];
    const float* bn1_mean  = (const float*)d_in[6];
    const float* bn1_var   = (const float*)d_in[7];
    const float* w2        = (const float*)d_in[8];
    const float* mlp_w     = (const float*)d_in[9];
    const float* mlp_b     = (const float*)d_in[10];
    const float* mlp_gamma = (const float*)d_in[11];
    const float* mlp_beta  = (const float*)d_in[12];
    const float* mlp_mean  = (const float*)d_in[13];
    const float* mlp_var   = (const float*)d_in[14];
    float* out = (float*)d_out;

    pack_xz_kernel<<<(NPTS + 255) / 256, 256>>>(x_feats, z_feats);
    transpose_idx_kernel<<<NPTS / 256, 256>>>(nbr_idx);

    stage1_kernel<<<NPTS / A_THREADS, A_THREADS>>>(
        w1, bn1_gamma, bn1_beta, bn1_mean, bn1_var);

    stage2_kernel<<<NPTS / TILE_P, B_THREADS>>>(
        w2, mlp_w, mlp_b,
        mlp_gamma, mlp_beta, mlp_mean, mlp_var, out);
}

// round 11
// speedup vs baseline: 2.4809x; 1.8772x over previous
#include <cuda_runtime.h>
#include <cuda_fp16.h>
#include <cstdint>

#define NPTS 131072
#define KNBR 27
#define FINC 3
#define FOUTC 32
#define EPSV 1e-5f

// static scratch (allocation rules forbid cudaMalloc)
__device__ __align__(16) __half g_h16[(size_t)NPTS * FOUTC];   // 8 MB fp16 h
__device__ float g_x4[(size_t)NPTS * 4];                       // 2 MB padded x
__device__ float g_z4[(size_t)NPTS * 4];                       // 2 MB padded z
__device__ int   g_idxT[(size_t)KNBR * NPTS];                  // 14 MB idx^T
__device__ __align__(16) __half g_w2t[(size_t)KNBR * FOUTC * FOUTC]; // [k][o][f]

typedef unsigned long long ull;
typedef unsigned int uint;

__device__ __forceinline__ ull pk2(float lo, float hi) {
    ull r; asm("mov.b64 %0, {%1, %2};" : "=l"(r) : "f"(lo), "f"(hi)); return r;
}
__device__ __forceinline__ void upk2(ull v, float& lo, float& hi) {
    asm("mov.b64 {%0, %1}, %2;" : "=f"(lo), "=f"(hi) : "l"(v));
}
__device__ __forceinline__ void ffma2(ull& d, ull a, ull b) {
    asm("fma.rn.f32x2 %0, %1, %2, %0;" : "+l"(d) : "l"(a), "l"(b));
}
__device__ __forceinline__ uint s2u(const void* p) {
    uint a;
    asm("{ .reg .u64 t; cvta.to.shared.u64 t, %1; cvt.u32.u64 %0, t; }"
        : "=r"(a) : "l"(p));
    return a;
}
__device__ __forceinline__ void sts128(uint addr, uint4 v) {
    asm volatile("st.shared.v4.b32 [%0], {%1, %2, %3, %4};"
                 :: "r"(addr), "r"(v.x), "r"(v.y), "r"(v.z), "r"(v.w));
}
__device__ __forceinline__ void ldsm4(uint addr, uint* r) {
    asm volatile("ldmatrix.sync.aligned.m8n8.x4.shared.b16 {%0,%1,%2,%3}, [%4];"
                 : "=r"(r[0]), "=r"(r[1]), "=r"(r[2]), "=r"(r[3]) : "r"(addr));
}
__device__ __forceinline__ void mma16816(float* c, const uint* a, uint b0, uint b1) {
    asm volatile(
        "mma.sync.aligned.m16n8k16.row.col.f32.f16.f16.f32 "
        "{%0,%1,%2,%3}, {%4,%5,%6,%7}, {%8,%9}, {%0,%1,%2,%3};"
        : "+f"(c[0]), "+f"(c[1]), "+f"(c[2]), "+f"(c[3])
        : "r"(a[0]), "r"(a[1]), "r"(a[2]), "r"(a[3]), "r"(b0), "r"(b1));
}
// swizzled offset within a tile of 64B rows (16B granularity)
__device__ __forceinline__ uint swoff(int row, int kseg) {
    return (uint)row * 64u + (uint)((kseg ^ ((row >> 1) & 3)) << 4);
}

// ---------------------------------------------------------------------------
// Pre-pass A: pack x_feats and z_feats [N,3] -> [N,4] float4
// ---------------------------------------------------------------------------
__global__ void __launch_bounds__(256) pack_xz_kernel(
    const float* __restrict__ x, const float* __restrict__ z)
{
    int n = blockIdx.x * 256 + threadIdx.x;
    if (n < NPTS) {
        float4 v;
        v.x = x[(size_t)n * 3 + 0];
        v.y = x[(size_t)n * 3 + 1];
        v.z = x[(size_t)n * 3 + 2];
        v.w = 0.f;
        ((float4*)g_x4)[n] = v;
        float4 w;
        w.x = z[(size_t)n * 3 + 0];
        w.y = z[(size_t)n * 3 + 1];
        w.z = z[(size_t)n * 3 + 2];
        w.w = 0.f;
        ((float4*)g_z4)[n] = w;
    }
}

// ---------------------------------------------------------------------------
// Pre-pass B: transpose nbr_idx [N,K] -> g_idxT [K,N]
// ---------------------------------------------------------------------------
__global__ void __launch_bounds__(256) transpose_idx_kernel(const int* __restrict__ nbr)
{
    __shared__ int sI[256 * KNBR];
    const int tid  = threadIdx.x;
    const int base = blockIdx.x * 256;
    for (int i = tid; i < 256 * KNBR; i += 256)
        sI[i] = nbr[(size_t)base * KNBR + i];
    __syncthreads();
#pragma unroll
    for (int k = 0; k < KNBR; k++)
        g_idxT[(size_t)k * NPTS + base + tid] = sI[tid * KNBR + k];
}

// ---------------------------------------------------------------------------
// Pre-pass C: w2 [k][f][o] fp32 -> g_w2t [k][o][f] fp16
// ---------------------------------------------------------------------------
__global__ void __launch_bounds__(256) w2t_kernel(const float* __restrict__ w2)
{
    int i = blockIdx.x * 256 + threadIdx.x;
    if (i < KNBR * FOUTC * FOUTC) {
        int k = i >> 10, r = i & 1023;
        int o = r >> 5, f = r & 31;
        g_w2t[i] = __float2half(w2[(size_t)k * 1024 + f * 32 + o]);
    }
}

// ---------------------------------------------------------------------------
// Stage 1: h = silu(bn(gather(x) @ w1)) -> fp16  (CUDA cores, f32x2)
// ---------------------------------------------------------------------------
#define A_THREADS 256

__global__ void __launch_bounds__(A_THREADS) stage1_kernel(
    const float* __restrict__ w1,
    const float* __restrict__ g1,
    const float* __restrict__ b1,
    const float* __restrict__ m1,
    const float* __restrict__ v1)
{
    __shared__ float w1s[KNBR * FINC * FOUTC];
    __shared__ float sScale[FOUTC], sShift[FOUTC];

    const int tid = threadIdx.x;
    const int n   = blockIdx.x * A_THREADS + tid;

    for (int i = tid; i < KNBR * FINC * FOUTC; i += A_THREADS) w1s[i] = w1[i];
    if (tid < FOUTC) {
        float s = rsqrtf(v1[tid] + EPSV) * g1[tid];
        sScale[tid] = s;
        sShift[tid] = b1[tid] - m1[tid] * s;
    }
    __syncthreads();

    ull acc[16];
#pragma unroll
    for (int q = 0; q < 16; q++) acc[q] = 0ULL;

    for (int k = 0; k < KNBR; k++) {
        int idx = __ldg(g_idxT + (size_t)k * NPTS + n);
        float4 xv = __ldg((const float4*)g_x4 + idx);
        ull px0 = pk2(xv.x, xv.x);
        ull px1 = pk2(xv.y, xv.y);
        ull px2 = pk2(xv.z, xv.z);
        const ulonglong2* w0p = (const ulonglong2*)&w1s[(k * 3 + 0) * FOUTC];
        const ulonglong2* w1p = (const ulonglong2*)&w1s[(k * 3 + 1) * FOUTC];
        const ulonglong2* w2p = (const ulonglong2*)&w1s[(k * 3 + 2) * FOUTC];
#pragma unroll
        for (int q = 0; q < 8; q++) {
            ulonglong2 a = w0p[q], b = w1p[q], c = w2p[q];
            ffma2(acc[q * 2 + 0], px0, a.x);
            ffma2(acc[q * 2 + 1], px0, a.y);
            ffma2(acc[q * 2 + 0], px1, b.x);
            ffma2(acc[q * 2 + 1], px1, b.y);
            ffma2(acc[q * 2 + 0], px2, c.x);
            ffma2(acc[q * 2 + 1], px2, c.y);
        }
    }

    uint4* hp = (uint4*)(g_h16 + (size_t)n * FOUTC);
#pragma unroll
    for (int c = 0; c < 4; c++) {
        float r[8];
#pragma unroll
        for (int j = 0; j < 4; j++) {
            float lo, hi;
            upk2(acc[c * 4 + j], lo, hi);
            r[j * 2 + 0] = lo;
            r[j * 2 + 1] = hi;
        }
        uint w[4];
#pragma unroll
        for (int j = 0; j < 8; j++) {
            int o = c * 8 + j;
            float v = r[j] * sScale[o] + sShift[o];
            float sig = 1.f / (1.f + __expf(-v));
            r[j] = v * sig;
        }
#pragma unroll
        for (int j = 0; j < 4; j++) {
            __half2 h2 = __floats2half2_rn(r[j * 2], r[j * 2 + 1]);
            w[j] = *(uint*)&h2;
        }
        hp[c] = make_uint4(w[0], w[1], w[2], w[3]);
    }
}

// ---------------------------------------------------------------------------
// Stage 2 (HMMA): per CTA of 128 points, D[128x32] in registers accumulates
// 27 gathered GEMMs A_k[128x32] @ w2t_k[32x32]^T via mma.m16n8k16 f16/f32.
// Warp w owns rows [32w, 32w+32): 2 m-tiles x 4 n-tiles, k=32 as 2 k-tiles.
// A/B smem tiles: 64B rows, swizzle off=row*64+((ks^((row>>1)&3))<<4)
//   (conflict-free for gather STS.128, A ldmatrix, B ldmatrix -- verified).
// Double-buffered, 1 syncthreads/k. Epilogue fuses point branch + dup store.
// ---------------------------------------------------------------------------
#define C_THREADS 128
#define TILE_P    128

__global__ void __launch_bounds__(C_THREADS) stage2_mma_kernel(
    const float* __restrict__ mlp_w,
    const float* __restrict__ mlp_b,
    const float* __restrict__ mg,
    const float* __restrict__ mbt,
    const float* __restrict__ mm,
    const float* __restrict__ mv,
    float* __restrict__ out)
{
    __shared__ __align__(1024) __half sA[2][TILE_P * 32];  // 2 x 8 KB
    __shared__ __align__(1024) __half sB[2][32 * 32];      // 2 x 2 KB
    __shared__ float sPar[6][FOUTC];

    const int tid   = threadIdx.x;
    const int lane  = tid & 31;
    const int wid   = tid >> 5;
    const int wbase = wid * 32;
    const int base  = blockIdx.x * TILE_P;

    const uint aAddr[2] = { s2u(sA[0]), s2u(sA[1]) };
    const uint bAddr[2] = { s2u(sB[0]), s2u(sB[1]) };

    if (tid < FOUTC) {
        float s = rsqrtf(__ldg(mv + tid) + EPSV) * __ldg(mg + tid);
        sPar[0][tid] = s;
        sPar[1][tid] = __ldg(mbt + tid) - __ldg(mm + tid) * s;
        sPar[2][tid] = __ldg(mlp_w + tid);
        sPar[3][tid] = __ldg(mlp_w + 32 + tid);
        sPar[4][tid] = __ldg(mlp_w + 64 + tid);
        sPar[5][tid] = __ldg(mlp_b + tid);
    }

    float acc[2][4][4];
#pragma unroll
    for (int mt = 0; mt < 2; mt++)
#pragma unroll
        for (int nt = 0; nt < 4; nt++)
#pragma unroll
            for (int c = 0; c < 4; c++) acc[mt][nt][c] = 0.f;

    // ---- gather neighbor k into buffer bs
    auto gather = [&](int k, int bs) {
        // A: thread tid owns point-row tid (64 B = 4 ksegs)
        int idx = __ldg(g_idxT + (size_t)k * NPTS + base + tid);
        const uint4* src = (const uint4*)(g_h16 + (size_t)idx * FOUTC);
        uint4 v0 = __ldg(src + 0);
        uint4 v1 = __ldg(src + 1);
        uint4 v2 = __ldg(src + 2);
        uint4 v3 = __ldg(src + 3);
        uint ab = aAddr[bs];
        sts128(ab + swoff(tid, 0), v0);
        sts128(ab + swoff(tid, 1), v1);
        sts128(ab + swoff(tid, 2), v2);
        sts128(ab + swoff(tid, 3), v3);
        // B: w2t[k] = 32 n-rows x 64 B = 128 x 16B chunks; thread owns one
        uint4 wv = __ldg((const uint4*)(g_w2t + (size_t)k * 1024) + tid);
        sts128(bAddr[bs] + swoff(tid >> 2, tid & 3), wv);
    };

    gather(0, 0);

    for (int k = 0; k < KNBR; k++) {
        __syncthreads();                 // buf[k&1] ready; other buf free
        if (k + 1 < KNBR) gather(k + 1, (k + 1) & 1);

        const uint aB = aAddr[k & 1];
        const uint bB = bAddr[k & 1];

        // A fragments: 2 m-tiles x 2 k-tiles
        uint a[2][2][4];
#pragma unroll
        for (int mt = 0; mt < 2; mt++)
#pragma unroll
            for (int kt = 0; kt < 2; kt++) {
                int r  = wbase + mt * 16 + (lane & 15);
                int ks = kt * 2 + (lane >> 4);
                ldsm4(aB + swoff(r, ks), a[mt][kt]);
            }
        // B fragments: 2 n-tile-pairs x 2 k-tiles
        // quad q=lane>>3: matrix = (ntile p*2 + (q>>1), kseg kt*2 + (q&1))
        uint b[2][2][4];
#pragma unroll
        for (int p = 0; p < 2; p++)
#pragma unroll
            for (int kt = 0; kt < 2; kt++) {
                int q  = lane >> 3;
                int n  = (p * 2 + (q >> 1)) * 8 + (lane & 7);
                int ks = kt * 2 + (q & 1);
                ldsm4(bB + swoff(n, ks), b[p][kt]);
            }
#pragma unroll
        for (int mt = 0; mt < 2; mt++)
#pragma unroll
            for (int nt = 0; nt < 4; nt++) {
                int p = nt >> 1, h = (nt & 1) * 2;
#pragma unroll
                for (int kt = 0; kt < 2; kt++)
                    mma16816(acc[mt][nt], a[mt][kt], b[p][kt][h], b[p][kt][h + 1]);
            }
    }

    // ---- epilogue: fuse point branch, duplicated store
    // c-fragment: c0,c1 = (row = mtile*16 + lane/4, cols 2(lane%4)+{0,1});
    //             c2,c3 = row+8.
    const int cb = 2 * (lane & 3);
#pragma unroll
    for (int mt = 0; mt < 2; mt++) {
#pragma unroll
        for (int rr = 0; rr < 2; rr++) {
            int row = wbase + mt * 16 + rr * 8 + (lane >> 2);
            int n   = base + row;
            float4 z4 = __ldg((const float4*)g_z4 + n);
#pragma unroll
            for (int nt = 0; nt < 4; nt++) {
                int c0 = nt * 8 + cb;
                float r0 = acc[mt][nt][rr * 2 + 0];
                float r1 = acc[mt][nt][rr * 2 + 1];
                float zv0 = z4.x * sPar[2][c0] + z4.y * sPar[3][c0]
                          + z4.z * sPar[4][c0] + sPar[5][c0];
                zv0 = fmaxf(zv0 * sPar[0][c0] + sPar[1][c0], 0.f);
                float zv1 = z4.x * sPar[2][c0+1] + z4.y * sPar[3][c0+1]
                          + z4.z * sPar[4][c0+1] + sPar[5][c0+1];
                zv1 = fmaxf(zv1 * sPar[0][c0+1] + sPar[1][c0+1], 0.f);
                float2 st = make_float2(r0 + zv0, r1 + zv1);
                *(float2*)(out + (size_t)n * FOUTC + c0) = st;
                *(float2*)(out + (size_t)(NPTS + n) * FOUTC + c0) = st;
            }
        }
    }
}

// ---------------------------------------------------------------------------
extern "C" void kernel_launch(void* const* d_in, const int* in_sizes, int n_in,
                              void* d_out, int out_size)
{
    const float* x_feats   = (const float*)d_in[0];
    const float* z_feats   = (const float*)d_in[1];
    const int*   nbr_idx   = (const int*)  d_in[2];
    const float* w1        = (const float*)d_in[3];
    const float* bn1_gamma = (const float*)d_in[4];
    const float* bn1_beta  = (const float*)d_in[5];
    const float* bn1_mean  = (const float*)d_in[6];
    const float* bn1_var   = (const float*)d_in[7];
    const float* w2        = (const float*)d_in[8];
    const float* mlp_w     = (const float*)d_in[9];
    const float* mlp_b     = (const float*)d_in[10];
    const float* mlp_gamma = (const float*)d_in[11];
    const float* mlp_beta  = (const float*)d_in[12];
    const float* mlp_mean  = (const float*)d_in[13];
    const float* mlp_var   = (const float*)d_in[14];
    float* out = (float*)d_out;

    pack_xz_kernel<<<(NPTS + 255) / 256, 256>>>(x_feats, z_feats);
    transpose_idx_kernel<<<NPTS / 256, 256>>>(nbr_idx);
    w2t_kernel<<<(KNBR * FOUTC * FOUTC + 255) / 256, 256>>>(w2);

    stage1_kernel<<<NPTS / A_THREADS, A_THREADS>>>(
        w1, bn1_gamma, bn1_beta, bn1_mean, bn1_var);

    stage2_mma_kernel<<<NPTS / TILE_P, C_THREADS>>>(
        mlp_w, mlp_b, mlp_gamma, mlp_beta, mlp_mean, mlp_var, out);
}

// round 13
// speedup vs baseline: 2.6776x; 1.0793x over previous
#include <cuda_runtime.h>
#include <cuda_fp16.h>
#include <cstdint>

#define NPTS 131072
#define KNBR 27
#define FINC 3
#define FOUTC 32
#define EPSV 1e-5f

// static scratch (allocation rules forbid cudaMalloc)
__device__ __align__(16) __half g_h16[(size_t)NPTS * FOUTC];   // 8 MB fp16 h
__device__ float g_x4[(size_t)NPTS * 4];                       // 2 MB padded x
__device__ float g_z4[(size_t)NPTS * 4];                       // 2 MB padded z
__device__ int   g_idxT[(size_t)KNBR * NPTS];                  // 14 MB idx^T
__device__ __align__(16) __half g_w2t[(size_t)KNBR * FOUTC * FOUTC]; // [k][o][f]

typedef unsigned long long ull;
typedef unsigned int uint;

__device__ __forceinline__ ull pk2(float lo, float hi) {
    ull r; asm("mov.b64 %0, {%1, %2};" : "=l"(r) : "f"(lo), "f"(hi)); return r;
}
__device__ __forceinline__ void upk2(ull v, float& lo, float& hi) {
    asm("mov.b64 {%0, %1}, %2;" : "=f"(lo), "=f"(hi) : "l"(v));
}
__device__ __forceinline__ void ffma2(ull& d, ull a, ull b) {
    asm("fma.rn.f32x2 %0, %1, %2, %0;" : "+l"(d) : "l"(a), "l"(b));
}
__device__ __forceinline__ uint s2u(const void* p) {
    uint a;
    asm("{ .reg .u64 t; cvta.to.shared.u64 t, %1; cvt.u32.u64 %0, t; }"
        : "=r"(a) : "l"(p));
    return a;
}
__device__ __forceinline__ void sts128(uint addr, uint4 v) {
    asm volatile("st.shared.v4.b32 [%0], {%1, %2, %3, %4};"
                 :: "r"(addr), "r"(v.x), "r"(v.y), "r"(v.z), "r"(v.w));
}
__device__ __forceinline__ void ldsm4(uint addr, uint* r) {
    asm volatile("ldmatrix.sync.aligned.m8n8.x4.shared.b16 {%0,%1,%2,%3}, [%4];"
                 : "=r"(r[0]), "=r"(r[1]), "=r"(r[2]), "=r"(r[3]) : "r"(addr));
}
__device__ __forceinline__ void mma16816(float* c, const uint* a, uint b0, uint b1) {
    asm volatile(
        "mma.sync.aligned.m16n8k16.row.col.f32.f16.f16.f32 "
        "{%0,%1,%2,%3}, {%4,%5,%6,%7}, {%8,%9}, {%0,%1,%2,%3};"
        : "+f"(c[0]), "+f"(c[1]), "+f"(c[2]), "+f"(c[3])
        : "r"(a[0]), "r"(a[1]), "r"(a[2]), "r"(a[3]), "r"(b0), "r"(b1));
}
// swizzled offset within a tile of 64B rows (16B granularity)
__device__ __forceinline__ uint swoff(int row, int kseg) {
    return (uint)row * 64u + (uint)((kseg ^ ((row >> 1) & 3)) << 4);
}

// ---------------------------------------------------------------------------
// Merged pre-pass: pack x/z [N,3]->[N,4], transpose nbr_idx, convert w2.
// grid = NPTS/256 blocks of 256 threads.
// ---------------------------------------------------------------------------
__global__ void __launch_bounds__(256) prep_kernel(
    const float* __restrict__ x, const float* __restrict__ z,
    const int* __restrict__ nbr, const float* __restrict__ w2)
{
    __shared__ int sI[256 * KNBR];
    const int tid  = threadIdx.x;
    const int base = blockIdx.x * 256;
    const int n    = base + tid;

    // pack x, z
    {
        float4 v;
        v.x = x[(size_t)n * 3 + 0];
        v.y = x[(size_t)n * 3 + 1];
        v.z = x[(size_t)n * 3 + 2];
        v.w = 0.f;
        ((float4*)g_x4)[n] = v;
        float4 w;
        w.x = z[(size_t)n * 3 + 0];
        w.y = z[(size_t)n * 3 + 1];
        w.z = z[(size_t)n * 3 + 2];
        w.w = 0.f;
        ((float4*)g_z4)[n] = w;
    }
    // w2 transpose+fp16: 27648 elements spread over the whole grid
    {
        int i = blockIdx.x * 256 + tid;           // reuse linear id
        int stride = gridDim.x * 256;
        for (; i < KNBR * FOUTC * FOUTC; i += stride) {
            int k = i >> 10, r = i & 1023;
            int o = r >> 5, f = r & 31;
            g_w2t[i] = __float2half(w2[(size_t)k * 1024 + f * 32 + o]);
        }
    }
    // idx transpose
    for (int i = tid; i < 256 * KNBR; i += 256)
        sI[i] = nbr[(size_t)base * KNBR + i];
    __syncthreads();
#pragma unroll
    for (int k = 0; k < KNBR; k++)
        g_idxT[(size_t)k * NPTS + base + tid] = sI[tid * KNBR + k];
}

// ---------------------------------------------------------------------------
// Stage 1: h = silu(bn(gather(x) @ w1)) -> fp16  (f32x2, pipelined gather)
// Rolling prefetch: indices 3 ahead, x-rows 2 ahead.
// ---------------------------------------------------------------------------
#define A_THREADS 256

__global__ void __launch_bounds__(A_THREADS) stage1_kernel(
    const float* __restrict__ w1,
    const float* __restrict__ g1,
    const float* __restrict__ b1,
    const float* __restrict__ m1,
    const float* __restrict__ v1)
{
    __shared__ float w1s[KNBR * FINC * FOUTC];
    __shared__ float sScale[FOUTC], sShift[FOUTC];

    const int tid = threadIdx.x;
    const int n   = blockIdx.x * A_THREADS + tid;

    for (int i = tid; i < KNBR * FINC * FOUTC; i += A_THREADS) w1s[i] = w1[i];
    if (tid < FOUTC) {
        float s = rsqrtf(v1[tid] + EPSV) * g1[tid];
        sScale[tid] = s;
        sShift[tid] = b1[tid] - m1[tid] * s;
    }
    __syncthreads();

    ull acc[16];
#pragma unroll
    for (int q = 0; q < 16; q++) acc[q] = 0ULL;

    // rolling prefetch state
    int i1 = __ldg(g_idxT + (size_t)0 * NPTS + n);
    int i2 = __ldg(g_idxT + (size_t)1 * NPTS + n);
    int i3 = __ldg(g_idxT + (size_t)2 * NPTS + n);
    float4 x0 = __ldg((const float4*)g_x4 + i1);
    float4 x1 = __ldg((const float4*)g_x4 + i2);

#pragma unroll
    for (int k = 0; k < KNBR; k++) {
        float4 xc = x0;
        x0 = x1;
        if (k + 2 < KNBR) x1 = __ldg((const float4*)g_x4 + i3);
        i1 = i2; i2 = i3;
        if (k + 3 < KNBR) i3 = __ldg(g_idxT + (size_t)(k + 3) * NPTS + n);

        ull px0 = pk2(xc.x, xc.x);
        ull px1 = pk2(xc.y, xc.y);
        ull px2 = pk2(xc.z, xc.z);
        const ulonglong2* w0p = (const ulonglong2*)&w1s[(k * 3 + 0) * FOUTC];
        const ulonglong2* w1p = (const ulonglong2*)&w1s[(k * 3 + 1) * FOUTC];
        const ulonglong2* w2p = (const ulonglong2*)&w1s[(k * 3 + 2) * FOUTC];
#pragma unroll
        for (int q = 0; q < 8; q++) {
            ulonglong2 a = w0p[q], b = w1p[q], c = w2p[q];
            ffma2(acc[q * 2 + 0], px0, a.x);
            ffma2(acc[q * 2 + 1], px0, a.y);
            ffma2(acc[q * 2 + 0], px1, b.x);
            ffma2(acc[q * 2 + 1], px1, b.y);
            ffma2(acc[q * 2 + 0], px2, c.x);
            ffma2(acc[q * 2 + 1], px2, c.y);
        }
    }

    uint4* hp = (uint4*)(g_h16 + (size_t)n * FOUTC);
#pragma unroll
    for (int c = 0; c < 4; c++) {
        float r[8];
#pragma unroll
        for (int j = 0; j < 4; j++) {
            float lo, hi;
            upk2(acc[c * 4 + j], lo, hi);
            r[j * 2 + 0] = lo;
            r[j * 2 + 1] = hi;
        }
        uint w[4];
#pragma unroll
        for (int j = 0; j < 8; j++) {
            int o = c * 8 + j;
            float v = r[j] * sScale[o] + sShift[o];
            float sig = 1.f / (1.f + __expf(-v));
            r[j] = v * sig;
        }
#pragma unroll
        for (int j = 0; j < 4; j++) {
            __half2 h2 = __floats2half2_rn(r[j * 2], r[j * 2 + 1]);
            w[j] = *(uint*)&h2;
        }
        hp[c] = make_uint4(w[0], w[1], w[2], w[3]);
    }
}

// ---------------------------------------------------------------------------
// Stage 2 (HMMA): D[128x32] += sum_k A_k[128x32] @ w2t_k[32x32]^T.
// Load/store-split pipeline: LDGs for k+1 issue BEFORE mma(k); STS after.
// idx prefetched 2 ahead in a rolling register. Double-buffered smem.
// ---------------------------------------------------------------------------
#define C_THREADS 128
#define TILE_P    128

__global__ void __launch_bounds__(C_THREADS) stage2_mma_kernel(
    const float* __restrict__ mlp_w,
    const float* __restrict__ mlp_b,
    const float* __restrict__ mg,
    const float* __restrict__ mbt,
    const float* __restrict__ mm,
    const float* __restrict__ mv,
    float* __restrict__ out)
{
    __shared__ __align__(1024) __half sA[2][TILE_P * 32];  // 2 x 8 KB
    __shared__ __align__(1024) __half sB[2][32 * 32];      // 2 x 2 KB
    __shared__ float sPar[6][FOUTC];

    const int tid   = threadIdx.x;
    const int lane  = tid & 31;
    const int wid   = tid >> 5;
    const int wbase = wid * 32;
    const int base  = blockIdx.x * TILE_P;

    const uint aAddr[2] = { s2u(sA[0]), s2u(sA[1]) };
    const uint bAddr[2] = { s2u(sB[0]), s2u(sB[1]) };

    if (tid < FOUTC) {
        float s = rsqrtf(__ldg(mv + tid) + EPSV) * __ldg(mg + tid);
        sPar[0][tid] = s;
        sPar[1][tid] = __ldg(mbt + tid) - __ldg(mm + tid) * s;
        sPar[2][tid] = __ldg(mlp_w + tid);
        sPar[3][tid] = __ldg(mlp_w + 32 + tid);
        sPar[4][tid] = __ldg(mlp_w + 64 + tid);
        sPar[5][tid] = __ldg(mlp_b + tid);
    }

    float acc[2][4][4];
#pragma unroll
    for (int mt = 0; mt < 2; mt++)
#pragma unroll
        for (int nt = 0; nt < 4; nt++)
#pragma unroll
            for (int c = 0; c < 4; c++) acc[mt][nt][c] = 0.f;

    // ---- prologue: fill buffer 0 with k=0; prefetch idx for k=1
    {
        int idx = __ldg(g_idxT + (size_t)0 * NPTS + base + tid);
        const uint4* src = (const uint4*)(g_h16 + (size_t)idx * FOUTC);
        uint4 v0 = __ldg(src + 0);
        uint4 v1 = __ldg(src + 1);
        uint4 v2 = __ldg(src + 2);
        uint4 v3 = __ldg(src + 3);
        sts128(aAddr[0] + swoff(tid, 0), v0);
        sts128(aAddr[0] + swoff(tid, 1), v1);
        sts128(aAddr[0] + swoff(tid, 2), v2);
        sts128(aAddr[0] + swoff(tid, 3), v3);
        uint4 wv = __ldg((const uint4*)(g_w2t + (size_t)0 * 1024) + tid);
        sts128(bAddr[0] + swoff(tid >> 2, tid & 3), wv);
    }
    int idxn = __ldg(g_idxT + (size_t)1 * NPTS + base + tid);  // idx for k=1

    for (int k = 0; k < KNBR; k++) {
        __syncthreads();   // buf[k&1] ready; buf[(k+1)&1] free (readers done)

        // ---- issue loads for k+1 (non-blocking until STS below)
        uint4 v0, v1, v2, v3, wv;
        const bool haveNext = (k + 1 < KNBR);
        if (haveNext) {
            const uint4* src = (const uint4*)(g_h16 + (size_t)idxn * FOUTC);
            v0 = __ldg(src + 0);
            v1 = __ldg(src + 1);
            v2 = __ldg(src + 2);
            v3 = __ldg(src + 3);
            wv = __ldg((const uint4*)(g_w2t + (size_t)(k + 1) * 1024) + tid);
        }
        if (k + 2 < KNBR)
            idxn = __ldg(g_idxT + (size_t)(k + 2) * NPTS + base + tid);

        // ---- compute on buf[k&1]
        const uint aB = aAddr[k & 1];
        const uint bB = bAddr[k & 1];

        uint a[2][2][4];
#pragma unroll
        for (int mt = 0; mt < 2; mt++)
#pragma unroll
            for (int kt = 0; kt < 2; kt++) {
                int r  = wbase + mt * 16 + (lane & 15);
                int ks = kt * 2 + (lane >> 4);
                ldsm4(aB + swoff(r, ks), a[mt][kt]);
            }
        uint b[2][2][4];
#pragma unroll
        for (int p = 0; p < 2; p++)
#pragma unroll
            for (int kt = 0; kt < 2; kt++) {
                int q  = lane >> 3;
                int nn = (p * 2 + (q >> 1)) * 8 + (lane & 7);
                int ks = kt * 2 + (q & 1);
                ldsm4(bB + swoff(nn, ks), b[p][kt]);
            }
#pragma unroll
        for (int mt = 0; mt < 2; mt++)
#pragma unroll
            for (int nt = 0; nt < 4; nt++) {
                int p = nt >> 1, h = (nt & 1) * 2;
#pragma unroll
                for (int kt = 0; kt < 2; kt++)
                    mma16816(acc[mt][nt], a[mt][kt], b[p][kt][h], b[p][kt][h + 1]);
            }

        // ---- store k+1 into the other buffer (stalls only here on LDGs)
        if (haveNext) {
            uint ab = aAddr[(k + 1) & 1];
            sts128(ab + swoff(tid, 0), v0);
            sts128(ab + swoff(tid, 1), v1);
            sts128(ab + swoff(tid, 2), v2);
            sts128(ab + swoff(tid, 3), v3);
            sts128(bAddr[(k + 1) & 1] + swoff(tid >> 2, tid & 3), wv);
        }
    }

    // ---- epilogue: fuse point branch, duplicated store
    const int cb = 2 * (lane & 3);
#pragma unroll
    for (int mt = 0; mt < 2; mt++) {
#pragma unroll
        for (int rr = 0; rr < 2; rr++) {
            int row = wbase + mt * 16 + rr * 8 + (lane >> 2);
            int n   = base + row;
            float4 z4 = __ldg((const float4*)g_z4 + n);
#pragma unroll
            for (int nt = 0; nt < 4; nt++) {
                int c0 = nt * 8 + cb;
                float r0 = acc[mt][nt][rr * 2 + 0];
                float r1 = acc[mt][nt][rr * 2 + 1];
                float zv0 = z4.x * sPar[2][c0] + z4.y * sPar[3][c0]
                          + z4.z * sPar[4][c0] + sPar[5][c0];
                zv0 = fmaxf(zv0 * sPar[0][c0] + sPar[1][c0], 0.f);
                float zv1 = z4.x * sPar[2][c0+1] + z4.y * sPar[3][c0+1]
                          + z4.z * sPar[4][c0+1] + sPar[5][c0+1];
                zv1 = fmaxf(zv1 * sPar[0][c0+1] + sPar[1][c0+1], 0.f);
                float2 st = make_float2(r0 + zv0, r1 + zv1);
                *(float2*)(out + (size_t)n * FOUTC + c0) = st;
                *(float2*)(out + (size_t)(NPTS + n) * FOUTC + c0) = st;
            }
        }
    }
}

// ---------------------------------------------------------------------------
extern "C" void kernel_launch(void* const* d_in, const int* in_sizes, int n_in,
                              void* d_out, int out_size)
{
    const float* x_feats   = (const float*)d_in[0];
    const float* z_feats   = (const float*)d_in[1];
    const int*   nbr_idx   = (const int*)  d_in[2];
    const float* w1        = (const float*)d_in[3];
    const float* bn1_gamma = (const float*)d_in[4];
    const float* bn1_beta  = (const float*)d_in[5];
    const float* bn1_mean  = (const float*)d_in[6];
    const float* bn1_var   = (const float*)d_in[7];
    const float* w2        = (const float*)d_in[8];
    const float* mlp_w     = (const float*)d_in[9];
    const float* mlp_b     = (const float*)d_in[10];
    const float* mlp_gamma = (const float*)d_in[11];
    const float* mlp_beta  = (const float*)d_in[12];
    const float* mlp_mean  = (const float*)d_in[13];
    const float* mlp_var   = (const float*)d_in[14];
    float* out = (float*)d_out;

    prep_kernel<<<NPTS / 256, 256>>>(x_feats, z_feats, nbr_idx, w2);

    stage1_kernel<<<NPTS / A_THREADS, A_THREADS>>>(
        w1, bn1_gamma, bn1_beta, bn1_mean, bn1_var);

    stage2_mma_kernel<<<NPTS / TILE_P, C_THREADS>>>(
        mlp_w, mlp_b, mlp_gamma, mlp_beta, mlp_mean, mlp_var, out);
}

// round 14
// speedup vs baseline: 3.3831x; 1.2635x over previous
#include <cuda_runtime.h>
#include <cuda_fp16.h>
#include <cstdint>

#define NPTS 131072
#define KNBR 27
#define FINC 3
#define FOUTC 32
#define EPSV 1e-5f

// static scratch (allocation rules forbid cudaMalloc)
__device__ __align__(16) __half g_h16[(size_t)NPTS * FOUTC];   // 8 MB fp16 h
__device__ float g_x4[(size_t)NPTS * 4];                       // 2 MB padded x
__device__ float g_z4[(size_t)NPTS * 4];                       // 2 MB padded z
__device__ int   g_idxT[(size_t)KNBR * NPTS];                  // 14 MB idx^T
__device__ __align__(16) __half g_w2t[(size_t)KNBR * FOUTC * FOUTC]; // [k][o][f]

typedef unsigned long long ull;
typedef unsigned int uint;

__device__ __forceinline__ ull pk2(float lo, float hi) {
    ull r; asm("mov.b64 %0, {%1, %2};" : "=l"(r) : "f"(lo), "f"(hi)); return r;
}
__device__ __forceinline__ void upk2(ull v, float& lo, float& hi) {
    asm("mov.b64 {%0, %1}, %2;" : "=f"(lo), "=f"(hi) : "l"(v));
}
__device__ __forceinline__ void ffma2(ull& d, ull a, ull b) {
    asm("fma.rn.f32x2 %0, %1, %2, %0;" : "+l"(d) : "l"(a), "l"(b));
}
__device__ __forceinline__ uint s2u(const void* p) {
    uint a;
    asm("{ .reg .u64 t; cvta.to.shared.u64 t, %1; cvt.u32.u64 %0, t; }"
        : "=r"(a) : "l"(p));
    return a;
}
__device__ __forceinline__ void sts128(uint addr, uint4 v) {
    asm volatile("st.shared.v4.b32 [%0], {%1, %2, %3, %4};"
                 :: "r"(addr), "r"(v.x), "r"(v.y), "r"(v.z), "r"(v.w));
}
__device__ __forceinline__ void ldsm4(uint addr, uint* r) {
    asm volatile("ldmatrix.sync.aligned.m8n8.x4.shared.b16 {%0,%1,%2,%3}, [%4];"
                 : "=r"(r[0]), "=r"(r[1]), "=r"(r[2]), "=r"(r[3]) : "r"(addr));
}
__device__ __forceinline__ void mma16816(float* c, const uint* a, uint b0, uint b1) {
    asm volatile(
        "mma.sync.aligned.m16n8k16.row.col.f32.f16.f16.f32 "
        "{%0,%1,%2,%3}, {%4,%5,%6,%7}, {%8,%9}, {%0,%1,%2,%3};"
        : "+f"(c[0]), "+f"(c[1]), "+f"(c[2]), "+f"(c[3])
        : "r"(a[0]), "r"(a[1]), "r"(a[2]), "r"(a[3]), "r"(b0), "r"(b1));
}
// swizzled offset within a tile of 64B rows (16B granularity)
__device__ __forceinline__ uint swoff(int row, int kseg) {
    return (uint)row * 64u + (uint)((kseg ^ ((row >> 1) & 3)) << 4);
}

// ---------------------------------------------------------------------------
// Merged pre-pass: pack x/z [N,3]->[N,4], transpose nbr_idx, convert w2.
// ---------------------------------------------------------------------------
__global__ void __launch_bounds__(256) prep_kernel(
    const float* __restrict__ x, const float* __restrict__ z,
    const int* __restrict__ nbr, const float* __restrict__ w2)
{
    __shared__ int sI[256 * KNBR];
    const int tid  = threadIdx.x;
    const int base = blockIdx.x * 256;
    const int n    = base + tid;

    {
        float4 v;
        v.x = x[(size_t)n * 3 + 0];
        v.y = x[(size_t)n * 3 + 1];
        v.z = x[(size_t)n * 3 + 2];
        v.w = 0.f;
        ((float4*)g_x4)[n] = v;
        float4 w;
        w.x = z[(size_t)n * 3 + 0];
        w.y = z[(size_t)n * 3 + 1];
        w.z = z[(size_t)n * 3 + 2];
        w.w = 0.f;
        ((float4*)g_z4)[n] = w;
    }
    {
        int i = blockIdx.x * 256 + tid;
        int stride = gridDim.x * 256;
        for (; i < KNBR * FOUTC * FOUTC; i += stride) {
            int k = i >> 10, r = i & 1023;
            int o = r >> 5, f = r & 31;
            g_w2t[i] = __float2half(w2[(size_t)k * 1024 + f * 32 + o]);
        }
    }
    for (int i = tid; i < 256 * KNBR; i += 256)
        sI[i] = nbr[(size_t)base * KNBR + i];
    __syncthreads();
#pragma unroll
    for (int k = 0; k < KNBR; k++)
        g_idxT[(size_t)k * NPTS + base + tid] = sI[tid * KNBR + k];
}

// ---------------------------------------------------------------------------
// Stage 1: h = silu(bn(gather(x) @ w1)) -> fp16.
// k processed in 3 chunks of 9: all 9 x4 gathers issue back-to-back (MLP=9),
// next chunk's 9 indices prefetched under the FMA block.
// ---------------------------------------------------------------------------
#define A_THREADS 256

__global__ void __launch_bounds__(A_THREADS) stage1_kernel(
    const float* __restrict__ w1,
    const float* __restrict__ g1,
    const float* __restrict__ b1,
    const float* __restrict__ m1,
    const float* __restrict__ v1)
{
    __shared__ float w1s[KNBR * FINC * FOUTC];
    __shared__ float sScale[FOUTC], sShift[FOUTC];

    const int tid = threadIdx.x;
    const int n   = blockIdx.x * A_THREADS + tid;

    for (int i = tid; i < KNBR * FINC * FOUTC; i += A_THREADS) w1s[i] = w1[i];
    if (tid < FOUTC) {
        float s = rsqrtf(v1[tid] + EPSV) * g1[tid];
        sScale[tid] = s;
        sShift[tid] = b1[tid] - m1[tid] * s;
    }
    __syncthreads();

    ull acc[16];
#pragma unroll
    for (int q = 0; q < 16; q++) acc[q] = 0ULL;

    int idxs[9];
#pragma unroll
    for (int j = 0; j < 9; j++)
        idxs[j] = __ldg(g_idxT + (size_t)j * NPTS + n);

#pragma unroll
    for (int c = 0; c < 3; c++) {
        // issue all 9 gathers (MLP = 9)
        float4 xv[9];
#pragma unroll
        for (int j = 0; j < 9; j++)
            xv[j] = __ldg((const float4*)g_x4 + idxs[j]);
        // prefetch next chunk's indices under the FMA block
        if (c < 2) {
#pragma unroll
            for (int j = 0; j < 9; j++)
                idxs[j] = __ldg(g_idxT + (size_t)(9 * (c + 1) + j) * NPTS + n);
        }
#pragma unroll
        for (int j = 0; j < 9; j++) {
            int k = c * 9 + j;
            ull px0 = pk2(xv[j].x, xv[j].x);
            ull px1 = pk2(xv[j].y, xv[j].y);
            ull px2 = pk2(xv[j].z, xv[j].z);
            const ulonglong2* w0p = (const ulonglong2*)&w1s[(k * 3 + 0) * FOUTC];
            const ulonglong2* w1p = (const ulonglong2*)&w1s[(k * 3 + 1) * FOUTC];
            const ulonglong2* w2p = (const ulonglong2*)&w1s[(k * 3 + 2) * FOUTC];
#pragma unroll
            for (int q = 0; q < 8; q++) {
                ulonglong2 a = w0p[q], b = w1p[q], cc = w2p[q];
                ffma2(acc[q * 2 + 0], px0, a.x);
                ffma2(acc[q * 2 + 1], px0, a.y);
                ffma2(acc[q * 2 + 0], px1, b.x);
                ffma2(acc[q * 2 + 1], px1, b.y);
                ffma2(acc[q * 2 + 0], px2, cc.x);
                ffma2(acc[q * 2 + 1], px2, cc.y);
            }
        }
    }

    uint4* hp = (uint4*)(g_h16 + (size_t)n * FOUTC);
#pragma unroll
    for (int c = 0; c < 4; c++) {
        float r[8];
#pragma unroll
        for (int j = 0; j < 4; j++) {
            float lo, hi;
            upk2(acc[c * 4 + j], lo, hi);
            r[j * 2 + 0] = lo;
            r[j * 2 + 1] = hi;
        }
        uint w[4];
#pragma unroll
        for (int j = 0; j < 8; j++) {
            int o = c * 8 + j;
            float v = r[j] * sScale[o] + sShift[o];
            float sig = 1.f / (1.f + __expf(-v));
            r[j] = v * sig;
        }
#pragma unroll
        for (int j = 0; j < 4; j++) {
            __half2 h2 = __floats2half2_rn(r[j * 2], r[j * 2 + 1]);
            w[j] = *(uint*)&h2;
        }
        hp[c] = make_uint4(w[0], w[1], w[2], w[3]);
    }
}

// ---------------------------------------------------------------------------
// Stage 2 (HMMA): D[128x32] += sum_k A_k[128x32] @ w2t_k[32x32]^T.
// Coalesced gather: 4 consecutive lanes load the 4 chunks of ONE h-row
// (row = 32p + tid>>2, fc = tid&3) -> 8 lines/warp-inst instead of 32.
// Load/store-split pipeline (LDG k+1 before mma k), double-buffered smem.
// ---------------------------------------------------------------------------
#define C_THREADS 128
#define TILE_P    128

__global__ void __launch_bounds__(C_THREADS) stage2_mma_kernel(
    const float* __restrict__ mlp_w,
    const float* __restrict__ mlp_b,
    const float* __restrict__ mg,
    const float* __restrict__ mbt,
    const float* __restrict__ mm,
    const float* __restrict__ mv,
    float* __restrict__ out)
{
    __shared__ __align__(1024) __half sA[2][TILE_P * 32];  // 2 x 8 KB
    __shared__ __align__(1024) __half sB[2][32 * 32];      // 2 x 2 KB
    __shared__ float sPar[6][FOUTC];

    const int tid   = threadIdx.x;
    const int lane  = tid & 31;
    const int wid   = tid >> 5;
    const int wbase = wid * 32;
    const int base  = blockIdx.x * TILE_P;
    const int rsub  = tid >> 2;        // 0..31: row within pass
    const int fc    = tid & 3;         // 16B chunk

    const uint aAddr[2] = { s2u(sA[0]), s2u(sA[1]) };
    const uint bAddr[2] = { s2u(sB[0]), s2u(sB[1]) };

    if (tid < FOUTC) {
        float s = rsqrtf(__ldg(mv + tid) + EPSV) * __ldg(mg + tid);
        sPar[0][tid] = s;
        sPar[1][tid] = __ldg(mbt + tid) - __ldg(mm + tid) * s;
        sPar[2][tid] = __ldg(mlp_w + tid);
        sPar[3][tid] = __ldg(mlp_w + 32 + tid);
        sPar[4][tid] = __ldg(mlp_w + 64 + tid);
        sPar[5][tid] = __ldg(mlp_b + tid);
    }

    float acc[2][4][4];
#pragma unroll
    for (int mt = 0; mt < 2; mt++)
#pragma unroll
        for (int nt = 0; nt < 4; nt++)
#pragma unroll
            for (int c = 0; c < 4; c++) acc[mt][nt][c] = 0.f;

    // ---- coalesced load of neighbor k's A chunks (4 lanes per row)
    auto loadK = [&](int k, uint4* v, uint4& wv) {
#pragma unroll
        for (int p = 0; p < 4; p++) {
            int row = 32 * p + rsub;
            int idx = __ldg(g_idxT + (size_t)k * NPTS + base + row);
            v[p] = __ldg((const uint4*)(g_h16 + (size_t)idx * FOUTC) + fc);
        }
        wv = __ldg((const uint4*)(g_w2t + (size_t)k * 1024) + tid);
    };
    auto storeK = [&](int bs, const uint4* v, uint4 wv) {
        uint ab = aAddr[bs];
#pragma unroll
        for (int p = 0; p < 4; p++)
            sts128(ab + swoff(32 * p + rsub, fc), v[p]);
        sts128(bAddr[bs] + swoff(rsub, fc), wv);
    };

    // ---- prologue: fill buffer 0 with k=0
    {
        uint4 v[4], wv;
        loadK(0, v, wv);
        storeK(0, v, wv);
    }

    for (int k = 0; k < KNBR; k++) {
        __syncthreads();   // buf[k&1] ready; buf[(k+1)&1] free (readers done)

        // ---- issue loads for k+1 (consumed by STS after the mma block)
        uint4 v[4], wv;
        const bool haveNext = (k + 1 < KNBR);
        if (haveNext) loadK(k + 1, v, wv);

        // ---- compute on buf[k&1]
        const uint aB = aAddr[k & 1];
        const uint bB = bAddr[k & 1];

        uint a[2][2][4];
#pragma unroll
        for (int mt = 0; mt < 2; mt++)
#pragma unroll
            for (int kt = 0; kt < 2; kt++) {
                int r  = wbase + mt * 16 + (lane & 15);
                int ks = kt * 2 + (lane >> 4);
                ldsm4(aB + swoff(r, ks), a[mt][kt]);
            }
        uint b[2][2][4];
#pragma unroll
        for (int p = 0; p < 2; p++)
#pragma unroll
            for (int kt = 0; kt < 2; kt++) {
                int q  = lane >> 3;
                int nn = (p * 2 + (q >> 1)) * 8 + (lane & 7);
                int ks = kt * 2 + (q & 1);
                ldsm4(bB + swoff(nn, ks), b[p][kt]);
            }
#pragma unroll
        for (int mt = 0; mt < 2; mt++)
#pragma unroll
            for (int nt = 0; nt < 4; nt++) {
                int p = nt >> 1, h = (nt & 1) * 2;
#pragma unroll
                for (int kt = 0; kt < 2; kt++)
                    mma16816(acc[mt][nt], a[mt][kt], b[p][kt][h], b[p][kt][h + 1]);
            }

        // ---- store k+1 into the other buffer (stalls only here on LDGs)
        if (haveNext) storeK((k + 1) & 1, v, wv);
    }

    // ---- epilogue: fuse point branch, duplicated store
    const int cb = 2 * (lane & 3);
#pragma unroll
    for (int mt = 0; mt < 2; mt++) {
#pragma unroll
        for (int rr = 0; rr < 2; rr++) {
            int row = wbase + mt * 16 + rr * 8 + (lane >> 2);
            int n   = base + row;
            float4 z4 = __ldg((const float4*)g_z4 + n);
#pragma unroll
            for (int nt = 0; nt < 4; nt++) {
                int c0 = nt * 8 + cb;
                float r0 = acc[mt][nt][rr * 2 + 0];
                float r1 = acc[mt][nt][rr * 2 + 1];
                float zv0 = z4.x * sPar[2][c0] + z4.y * sPar[3][c0]
                          + z4.z * sPar[4][c0] + sPar[5][c0];
                zv0 = fmaxf(zv0 * sPar[0][c0] + sPar[1][c0], 0.f);
                float zv1 = z4.x * sPar[2][c0+1] + z4.y * sPar[3][c0+1]
                          + z4.z * sPar[4][c0+1] + sPar[5][c0+1];
                zv1 = fmaxf(zv1 * sPar[0][c0+1] + sPar[1][c0+1], 0.f);
                float2 st = make_float2(r0 + zv0, r1 + zv1);
                *(float2*)(out + (size_t)n * FOUTC + c0) = st;
                *(float2*)(out + (size_t)(NPTS + n) * FOUTC + c0) = st;
            }
        }
    }
}

// ---------------------------------------------------------------------------
extern "C" void kernel_launch(void* const* d_in, const int* in_sizes, int n_in,
                              void* d_out, int out_size)
{
    const float* x_feats   = (const float*)d_in[0];
    const float* z_feats   = (const float*)d_in[1];
    const int*   nbr_idx   = (const int*)  d_in[2];
    const float* w1        = (const float*)d_in[3];
    const float* bn1_gamma = (const float*)d_in[4];
    const float* bn1_beta  = (const float*)d_in[5];
    const float* bn1_mean  = (const float*)d_in[6];
    const float* bn1_var   = (const float*)d_in[7];
    const float* w2        = (const float*)d_in[8];
    const float* mlp_w     = (const float*)d_in[9];
    const float* mlp_b     = (const float*)d_in[10];
    const float* mlp_gamma = (const float*)d_in[11];
    const float* mlp_beta  = (const float*)d_in[12];
    const float* mlp_mean  = (const float*)d_in[13];
    const float* mlp_var   = (const float*)d_in[14];
    float* out = (float*)d_out;

    prep_kernel<<<NPTS / 256, 256>>>(x_feats, z_feats, nbr_idx, w2);

    stage1_kernel<<<NPTS / A_THREADS, A_THREADS>>>(
        w1, bn1_gamma, bn1_beta, bn1_mean, bn1_var);

    stage2_mma_kernel<<<NPTS / TILE_P, C_THREADS>>>(
        mlp_w, mlp_b, mlp_gamma, mlp_beta, mlp_mean, mlp_var, out);
}

// round 15
// speedup vs baseline: 3.4376x; 1.0161x over previous
#include <cuda_runtime.h>
#include <cuda_fp16.h>
#include <cstdint>

#define NPTS 131072
#define KNBR 27
#define FINC 3
#define FOUTC 32
#define EPSV 1e-5f

// static scratch (allocation rules forbid cudaMalloc)
__device__ __align__(16) __half g_h16[(size_t)NPTS * FOUTC];   // 8 MB fp16 h
__device__ float g_x4[(size_t)NPTS * 4];                       // 2 MB padded x
__device__ float g_z4[(size_t)NPTS * 4];                       // 2 MB padded z
__device__ int   g_idxT[(size_t)KNBR * NPTS];                  // 14 MB idx^T
__device__ __align__(16) __half g_w2t[(size_t)KNBR * FOUTC * FOUTC]; // [k][o][f]

typedef unsigned long long ull;
typedef unsigned int uint;

__device__ __forceinline__ ull pk2(float lo, float hi) {
    ull r; asm("mov.b64 %0, {%1, %2};" : "=l"(r) : "f"(lo), "f"(hi)); return r;
}
__device__ __forceinline__ void upk2(ull v, float& lo, float& hi) {
    asm("mov.b64 {%0, %1}, %2;" : "=f"(lo), "=f"(hi) : "l"(v));
}
__device__ __forceinline__ void ffma2(ull& d, ull a, ull b) {
    asm("fma.rn.f32x2 %0, %1, %2, %0;" : "+l"(d) : "l"(a), "l"(b));
}
__device__ __forceinline__ uint s2u(const void* p) {
    uint a;
    asm("{ .reg .u64 t; cvta.to.shared.u64 t, %1; cvt.u32.u64 %0, t; }"
        : "=r"(a) : "l"(p));
    return a;
}
__device__ __forceinline__ void sts128(uint addr, uint4 v) {
    asm volatile("st.shared.v4.b32 [%0], {%1, %2, %3, %4};"
                 :: "r"(addr), "r"(v.x), "r"(v.y), "r"(v.z), "r"(v.w));
}
__device__ __forceinline__ void ldsm4(uint addr, uint* r) {
    asm volatile("ldmatrix.sync.aligned.m8n8.x4.shared.b16 {%0,%1,%2,%3}, [%4];"
                 : "=r"(r[0]), "=r"(r[1]), "=r"(r[2]), "=r"(r[3]) : "r"(addr));
}
__device__ __forceinline__ void mma16816(float* c, const uint* a, uint b0, uint b1) {
    asm volatile(
        "mma.sync.aligned.m16n8k16.row.col.f32.f16.f16.f32 "
        "{%0,%1,%2,%3}, {%4,%5,%6,%7}, {%8,%9}, {%0,%1,%2,%3};"
        : "+f"(c[0]), "+f"(c[1]), "+f"(c[2]), "+f"(c[3])
        : "r"(a[0]), "r"(a[1]), "r"(a[2]), "r"(a[3]), "r"(b0), "r"(b1));
}
// swizzled offset within a tile of 64B rows (16B granularity)
__device__ __forceinline__ uint swoff(int row, int kseg) {
    return (uint)row * 64u + (uint)((kseg ^ ((row >> 1) & 3)) << 4);
}

// ---------------------------------------------------------------------------
// Merged pre-pass: pack x/z [N,3]->[N,4], transpose nbr_idx, convert w2.
// ---------------------------------------------------------------------------
__global__ void __launch_bounds__(256) prep_kernel(
    const float* __restrict__ x, const float* __restrict__ z,
    const int* __restrict__ nbr, const float* __restrict__ w2)
{
    __shared__ int sI[256 * KNBR];
    const int tid  = threadIdx.x;
    const int base = blockIdx.x * 256;
    const int n    = base + tid;

    {
        float4 v;
        v.x = x[(size_t)n * 3 + 0];
        v.y = x[(size_t)n * 3 + 1];
        v.z = x[(size_t)n * 3 + 2];
        v.w = 0.f;
        ((float4*)g_x4)[n] = v;
        float4 w;
        w.x = z[(size_t)n * 3 + 0];
        w.y = z[(size_t)n * 3 + 1];
        w.z = z[(size_t)n * 3 + 2];
        w.w = 0.f;
        ((float4*)g_z4)[n] = w;
    }
    {
        int i = blockIdx.x * 256 + tid;
        int stride = gridDim.x * 256;
        for (; i < KNBR * FOUTC * FOUTC; i += stride) {
            int k = i >> 10, r = i & 1023;
            int o = r >> 5, f = r & 31;
            g_w2t[i] = __float2half(w2[(size_t)k * 1024 + f * 32 + o]);
        }
    }
    for (int i = tid; i < 256 * KNBR; i += 256)
        sI[i] = nbr[(size_t)base * KNBR + i];
    __syncthreads();
#pragma unroll
    for (int k = 0; k < KNBR; k++)
        g_idxT[(size_t)k * NPTS + base + tid] = sI[tid * KNBR + k];
}

// ---------------------------------------------------------------------------
// Stage 1: h = silu(bn(gather(x) @ w1)) -> fp16.
// k in 3 chunks of 9: 9 gathers issue back-to-back (MLP=9); next chunk's
// indices prefetched under the FMA block.
// ---------------------------------------------------------------------------
#define A_THREADS 256

__global__ void __launch_bounds__(A_THREADS) stage1_kernel(
    const float* __restrict__ w1,
    const float* __restrict__ g1,
    const float* __restrict__ b1,
    const float* __restrict__ m1,
    const float* __restrict__ v1)
{
    __shared__ float w1s[KNBR * FINC * FOUTC];
    __shared__ float sScale[FOUTC], sShift[FOUTC];

    const int tid = threadIdx.x;
    const int n   = blockIdx.x * A_THREADS + tid;

    for (int i = tid; i < KNBR * FINC * FOUTC; i += A_THREADS) w1s[i] = w1[i];
    if (tid < FOUTC) {
        float s = rsqrtf(v1[tid] + EPSV) * g1[tid];
        sScale[tid] = s;
        sShift[tid] = b1[tid] - m1[tid] * s;
    }
    __syncthreads();

    ull acc[16];
#pragma unroll
    for (int q = 0; q < 16; q++) acc[q] = 0ULL;

    int idxs[9];
#pragma unroll
    for (int j = 0; j < 9; j++)
        idxs[j] = __ldg(g_idxT + (size_t)j * NPTS + n);

#pragma unroll
    for (int c = 0; c < 3; c++) {
        float4 xv[9];
#pragma unroll
        for (int j = 0; j < 9; j++)
            xv[j] = __ldg((const float4*)g_x4 + idxs[j]);
        if (c < 2) {
#pragma unroll
            for (int j = 0; j < 9; j++)
                idxs[j] = __ldg(g_idxT + (size_t)(9 * (c + 1) + j) * NPTS + n);
        }
#pragma unroll
        for (int j = 0; j < 9; j++) {
            int k = c * 9 + j;
            ull px0 = pk2(xv[j].x, xv[j].x);
            ull px1 = pk2(xv[j].y, xv[j].y);
            ull px2 = pk2(xv[j].z, xv[j].z);
            const ulonglong2* w0p = (const ulonglong2*)&w1s[(k * 3 + 0) * FOUTC];
            const ulonglong2* w1p = (const ulonglong2*)&w1s[(k * 3 + 1) * FOUTC];
            const ulonglong2* w2p = (const ulonglong2*)&w1s[(k * 3 + 2) * FOUTC];
#pragma unroll
            for (int q = 0; q < 8; q++) {
                ulonglong2 a = w0p[q], b = w1p[q], cc = w2p[q];
                ffma2(acc[q * 2 + 0], px0, a.x);
                ffma2(acc[q * 2 + 1], px0, a.y);
                ffma2(acc[q * 2 + 0], px1, b.x);
                ffma2(acc[q * 2 + 1], px1, b.y);
                ffma2(acc[q * 2 + 0], px2, cc.x);
                ffma2(acc[q * 2 + 1], px2, cc.y);
            }
        }
    }

    uint4* hp = (uint4*)(g_h16 + (size_t)n * FOUTC);
#pragma unroll
    for (int c = 0; c < 4; c++) {
        float r[8];
#pragma unroll
        for (int j = 0; j < 4; j++) {
            float lo, hi;
            upk2(acc[c * 4 + j], lo, hi);
            r[j * 2 + 0] = lo;
            r[j * 2 + 1] = hi;
        }
        uint w[4];
#pragma unroll
        for (int j = 0; j < 8; j++) {
            int o = c * 8 + j;
            float v = r[j] * sScale[o] + sShift[o];
            float sig = 1.f / (1.f + __expf(-v));
            r[j] = v * sig;
        }
#pragma unroll
        for (int j = 0; j < 4; j++) {
            __half2 h2 = __floats2half2_rn(r[j * 2], r[j * 2 + 1]);
            w[j] = *(uint*)&h2;
        }
        hp[c] = make_uint4(w[0], w[1], w[2], w[3]);
    }
}

// ---------------------------------------------------------------------------
// Stage 2 (HMMA): D[256x32] += sum_k A_k[256x32] @ w2t_k[32x32]^T per CTA.
// 256 threads / 8 warps; warp w owns rows [32w, 32w+32).
// Coalesced gather (4 lanes per row), STS swizzle conflict-free (verified).
// Deep pipeline: LDG for k+2 issued at iter k (full-iteration cover);
// STS for k+1 after the mma block; double-buffered smem, register rotation.
// B (w2t) handled by threads < 128 only.
// ---------------------------------------------------------------------------
#define C_THREADS 256
#define TILE_P    256

__global__ void __launch_bounds__(C_THREADS) stage2_mma_kernel(
    const float* __restrict__ mlp_w,
    const float* __restrict__ mlp_b,
    const float* __restrict__ mg,
    const float* __restrict__ mbt,
    const float* __restrict__ mm,
    const float* __restrict__ mv,
    float* __restrict__ out)
{
    __shared__ __align__(1024) __half sA[2][TILE_P * 32];  // 2 x 16 KB
    __shared__ __align__(1024) __half sB[2][32 * 32];      // 2 x 2 KB
    __shared__ float sPar[6][FOUTC];

    const int tid   = threadIdx.x;
    const int lane  = tid & 31;
    const int wid   = tid >> 5;
    const int wbase = wid * 32;
    const int base  = blockIdx.x * TILE_P;
    const int rsub  = tid >> 2;        // 0..63: row within 64-row pass
    const int fc    = tid & 3;         // 16B chunk
    const bool doB  = (tid < 128);

    const uint aAddr[2] = { s2u(sA[0]), s2u(sA[1]) };
    const uint bAddr[2] = { s2u(sB[0]), s2u(sB[1]) };

    if (tid < FOUTC) {
        float s = rsqrtf(__ldg(mv + tid) + EPSV) * __ldg(mg + tid);
        sPar[0][tid] = s;
        sPar[1][tid] = __ldg(mbt + tid) - __ldg(mm + tid) * s;
        sPar[2][tid] = __ldg(mlp_w + tid);
        sPar[3][tid] = __ldg(mlp_w + 32 + tid);
        sPar[4][tid] = __ldg(mlp_w + 64 + tid);
        sPar[5][tid] = __ldg(mlp_b + tid);
    }

    float acc[2][4][4];
#pragma unroll
    for (int mt = 0; mt < 2; mt++)
#pragma unroll
        for (int nt = 0; nt < 4; nt++)
#pragma unroll
            for (int c = 0; c < 4; c++) acc[mt][nt][c] = 0.f;

    // ---- coalesced load of neighbor k (4 lanes per row; 4 rows per thread)
    auto loadK = [&](int k, uint4* v, uint4& wv) {
#pragma unroll
        for (int p = 0; p < 4; p++) {
            int row = 64 * p + rsub;
            int idx = __ldg(g_idxT + (size_t)k * NPTS + base + row);
            v[p] = __ldg((const uint4*)(g_h16 + (size_t)idx * FOUTC) + fc);
        }
        if (doB)
            wv = __ldg((const uint4*)(g_w2t + (size_t)k * 1024) + tid);
    };
    auto storeK = [&](int bs, const uint4* v, uint4 wv) {
        uint ab = aAddr[bs];
#pragma unroll
        for (int p = 0; p < 4; p++)
            sts128(ab + swoff(64 * p + rsub, fc), v[p]);
        if (doB)
            sts128(bAddr[bs] + swoff(tid >> 2, tid & 3), wv);
    };

    // ---- prologue: k=0 into buf0; k=1 loaded into rotation regs
    {
        uint4 v[4], wv;
        loadK(0, v, wv);
        storeK(0, v, wv);
    }
    uint4 vr[4], wr;
    loadK(1, vr, wr);

    for (int k = 0; k < KNBR; k++) {
        __syncthreads();   // buf[k&1] ready; buf[(k+1)&1] free (readers done)

        // ---- issue loads for k+2 (consumed by STS in the NEXT iteration)
        uint4 vn[4], wn;
        if (k + 2 < KNBR) loadK(k + 2, vn, wn);

        // ---- compute on buf[k&1]
        const uint aB = aAddr[k & 1];
        const uint bB = bAddr[k & 1];

        uint a[2][2][4];
#pragma unroll
        for (int mt = 0; mt < 2; mt++)
#pragma unroll
            for (int kt = 0; kt < 2; kt++) {
                int r  = wbase + mt * 16 + (lane & 15);
                int ks = kt * 2 + (lane >> 4);
                ldsm4(aB + swoff(r, ks), a[mt][kt]);
            }
        uint b[2][2][4];
#pragma unroll
        for (int p = 0; p < 2; p++)
#pragma unroll
            for (int kt = 0; kt < 2; kt++) {
                int q  = lane >> 3;
                int nn = (p * 2 + (q >> 1)) * 8 + (lane & 7);
                int ks = kt * 2 + (q & 1);
                ldsm4(bB + swoff(nn, ks), b[p][kt]);
            }
#pragma unroll
        for (int mt = 0; mt < 2; mt++)
#pragma unroll
            for (int nt = 0; nt < 4; nt++) {
                int p = nt >> 1, h = (nt & 1) * 2;
#pragma unroll
                for (int kt = 0; kt < 2; kt++)
                    mma16816(acc[mt][nt], a[mt][kt], b[p][kt][h], b[p][kt][h + 1]);
            }

        // ---- store k+1 (regs loaded one full iteration ago) + rotate
        if (k + 1 < KNBR) {
            storeK((k + 1) & 1, vr, wr);
#pragma unroll
            for (int p = 0; p < 4; p++) vr[p] = vn[p];
            wr = wn;
        }
    }

    // ---- epilogue: fuse point branch, duplicated store
    const int cb = 2 * (lane & 3);
#pragma unroll
    for (int mt = 0; mt < 2; mt++) {
#pragma unroll
        for (int rr = 0; rr < 2; rr++) {
            int row = wbase + mt * 16 + rr * 8 + (lane >> 2);
            int n   = base + row;
            float4 z4 = __ldg((const float4*)g_z4 + n);
#pragma unroll
            for (int nt = 0; nt < 4; nt++) {
                int c0 = nt * 8 + cb;
                float r0 = acc[mt][nt][rr * 2 + 0];
                float r1 = acc[mt][nt][rr * 2 + 1];
                float zv0 = z4.x * sPar[2][c0] + z4.y * sPar[3][c0]
                          + z4.z * sPar[4][c0] + sPar[5][c0];
                zv0 = fmaxf(zv0 * sPar[0][c0] + sPar[1][c0], 0.f);
                float zv1 = z4.x * sPar[2][c0+1] + z4.y * sPar[3][c0+1]
                          + z4.z * sPar[4][c0+1] + sPar[5][c0+1];
                zv1 = fmaxf(zv1 * sPar[0][c0+1] + sPar[1][c0+1], 0.f);
                float2 st = make_float2(r0 + zv0, r1 + zv1);
                *(float2*)(out + (size_t)n * FOUTC + c0) = st;
                *(float2*)(out + (size_t)(NPTS + n) * FOUTC + c0) = st;
            }
        }
    }
}

// ---------------------------------------------------------------------------
extern "C" void kernel_launch(void* const* d_in, const int* in_sizes, int n_in,
                              void* d_out, int out_size)
{
    const float* x_feats   = (const float*)d_in[0];
    const float* z_feats   = (const float*)d_in[1];
    const int*   nbr_idx   = (const int*)  d_in[2];
    const float* w1        = (const float*)d_in[3];
    const float* bn1_gamma = (const float*)d_in[4];
    const float* bn1_beta  = (const float*)d_in[5];
    const float* bn1_mean  = (const float*)d_in[6];
    const float* bn1_var   = (const float*)d_in[7];
    const float* w2        = (const float*)d_in[8];
    const float* mlp_w     = (const float*)d_in[9];
    const float* mlp_b     = (const float*)d_in[10];
    const float* mlp_gamma = (const float*)d_in[11];
    const float* mlp_beta  = (const float*)d_in[12];
    const float* mlp_mean  = (const float*)d_in[13];
    const float* mlp_var   = (const float*)d_in[14];
    float* out = (float*)d_out;

    prep_kernel<<<NPTS / 256, 256>>>(x_feats, z_feats, nbr_idx, w2);

    stage1_kernel<<<NPTS / A_THREADS, A_THREADS>>>(
        w1, bn1_gamma, bn1_beta, bn1_mean, bn1_var);

    stage2_mma_kernel<<<NPTS / TILE_P, C_THREADS>>>(
        mlp_w, mlp_b, mlp_gamma, mlp_beta, mlp_mean, mlp_var, out);
}

// round 16
// speedup vs baseline: 4.0885x; 1.1894x over previous
#include <cuda_runtime.h>
#include <cuda_fp16.h>
#include <cstdint>

#define NPTS 131072
#define KNBR 27
#define FINC 3
#define FOUTC 32
#define EPSV 1e-5f

// static scratch (allocation rules forbid cudaMalloc)
__device__ __align__(16) __half g_h16[(size_t)NPTS * FOUTC];   // 8 MB fp16 h
__device__ float g_x4[(size_t)NPTS * 4];                       // 2 MB padded x
__device__ float g_z4[(size_t)NPTS * 4];                       // 2 MB padded z
__device__ __align__(16) __half g_w2t[(size_t)KNBR * FOUTC * FOUTC]; // [k][o][f]

typedef unsigned long long ull;
typedef unsigned int uint;

__device__ __forceinline__ ull pk2(float lo, float hi) {
    ull r; asm("mov.b64 %0, {%1, %2};" : "=l"(r) : "f"(lo), "f"(hi)); return r;
}
__device__ __forceinline__ void upk2(ull v, float& lo, float& hi) {
    asm("mov.b64 {%0, %1}, %2;" : "=f"(lo), "=f"(hi) : "l"(v));
}
__device__ __forceinline__ void ffma2(ull& d, ull a, ull b) {
    asm("fma.rn.f32x2 %0, %1, %2, %0;" : "+l"(d) : "l"(a), "l"(b));
}
__device__ __forceinline__ uint s2u(const void* p) {
    uint a;
    asm("{ .reg .u64 t; cvta.to.shared.u64 t, %1; cvt.u32.u64 %0, t; }"
        : "=r"(a) : "l"(p));
    return a;
}
__device__ __forceinline__ void cpa16(uint saddr, const void* g) {
    asm volatile("cp.async.cg.shared.global [%0], [%1], 16;"
                 :: "r"(saddr), "l"(__cvta_generic_to_global(g)) : "memory");
}
#define CP_COMMIT()  asm volatile("cp.async.commit_group;" ::: "memory")
#define CP_WAIT1()   asm volatile("cp.async.wait_group 1;" ::: "memory")
__device__ __forceinline__ void ldsm4(uint addr, uint* r) {
    asm volatile("ldmatrix.sync.aligned.m8n8.x4.shared.b16 {%0,%1,%2,%3}, [%4];"
                 : "=r"(r[0]), "=r"(r[1]), "=r"(r[2]), "=r"(r[3]) : "r"(addr));
}
__device__ __forceinline__ void mma16816(float* c, const uint* a, uint b0, uint b1) {
    asm volatile(
        "mma.sync.aligned.m16n8k16.row.col.f32.f16.f16.f32 "
        "{%0,%1,%2,%3}, {%4,%5,%6,%7}, {%8,%9}, {%0,%1,%2,%3};"
        : "+f"(c[0]), "+f"(c[1]), "+f"(c[2]), "+f"(c[3])
        : "r"(a[0]), "r"(a[1]), "r"(a[2]), "r"(a[3]), "r"(b0), "r"(b1));
}
// swizzled offset within a tile of 64B rows (16B granularity)
__device__ __forceinline__ uint swoff(int row, int kseg) {
    return (uint)row * 64u + (uint)((kseg ^ ((row >> 1) & 3)) << 4);
}

// ---------------------------------------------------------------------------
// Pre-pass: pack x/z [N,3]->[N,4] float4, convert w2 -> [k][o][f] fp16.
// ---------------------------------------------------------------------------
__global__ void __launch_bounds__(256) prep_kernel(
    const float* __restrict__ x, const float* __restrict__ z,
    const float* __restrict__ w2)
{
    const int tid = threadIdx.x;
    const int n   = blockIdx.x * 256 + tid;

    {
        float4 v;
        v.x = x[(size_t)n * 3 + 0];
        v.y = x[(size_t)n * 3 + 1];
        v.z = x[(size_t)n * 3 + 2];
        v.w = 0.f;
        ((float4*)g_x4)[n] = v;
        float4 w;
        w.x = z[(size_t)n * 3 + 0];
        w.y = z[(size_t)n * 3 + 1];
        w.z = z[(size_t)n * 3 + 2];
        w.w = 0.f;
        ((float4*)g_z4)[n] = w;
    }
    {
        int i = blockIdx.x * 256 + tid;
        int stride = gridDim.x * 256;
        for (; i < KNBR * FOUTC * FOUTC; i += stride) {
            int k = i >> 10, r = i & 1023;
            int o = r >> 5, f = r & 31;
            g_w2t[i] = __float2half(w2[(size_t)k * 1024 + f * 32 + o]);
        }
    }
}

// ---------------------------------------------------------------------------
// Stage 1: h = silu(bn(gather(x) @ w1)) -> fp16.
// Indices staged in smem (coalesced from nbr_idx, no global transpose).
// k in 3 chunks of 9: 9 gathers issue back-to-back (MLP=9).
// ---------------------------------------------------------------------------
#define A_THREADS 256

__global__ void __launch_bounds__(A_THREADS) stage1_kernel(
    const int*   __restrict__ nbr,
    const float* __restrict__ w1,
    const float* __restrict__ g1,
    const float* __restrict__ b1,
    const float* __restrict__ m1,
    const float* __restrict__ v1)
{
    __shared__ float w1s[KNBR * FINC * FOUTC];
    __shared__ float sScale[FOUTC], sShift[FOUTC];
    __shared__ int   sIdx[A_THREADS * KNBR];   // [pt][k], 27 KB

    const int tid  = threadIdx.x;
    const int base = blockIdx.x * A_THREADS;
    const int n    = base + tid;

    for (int i = tid; i < KNBR * FINC * FOUTC; i += A_THREADS) w1s[i] = w1[i];
    for (int i = tid; i < A_THREADS * KNBR; i += A_THREADS)
        sIdx[i] = nbr[(size_t)base * KNBR + i];
    if (tid < FOUTC) {
        float s = rsqrtf(v1[tid] + EPSV) * g1[tid];
        sScale[tid] = s;
        sShift[tid] = b1[tid] - m1[tid] * s;
    }
    __syncthreads();

    ull acc[16];
#pragma unroll
    for (int q = 0; q < 16; q++) acc[q] = 0ULL;

#pragma unroll
    for (int c = 0; c < 3; c++) {
        int idxs[9];
#pragma unroll
        for (int j = 0; j < 9; j++)
            idxs[j] = sIdx[tid * KNBR + c * 9 + j];
        float4 xv[9];
#pragma unroll
        for (int j = 0; j < 9; j++)
            xv[j] = __ldg((const float4*)g_x4 + idxs[j]);
#pragma unroll
        for (int j = 0; j < 9; j++) {
            int k = c * 9 + j;
            ull px0 = pk2(xv[j].x, xv[j].x);
            ull px1 = pk2(xv[j].y, xv[j].y);
            ull px2 = pk2(xv[j].z, xv[j].z);
            const ulonglong2* w0p = (const ulonglong2*)&w1s[(k * 3 + 0) * FOUTC];
            const ulonglong2* w1p = (const ulonglong2*)&w1s[(k * 3 + 1) * FOUTC];
            const ulonglong2* w2p = (const ulonglong2*)&w1s[(k * 3 + 2) * FOUTC];
#pragma unroll
            for (int q = 0; q < 8; q++) {
                ulonglong2 a = w0p[q], b = w1p[q], cc = w2p[q];
                ffma2(acc[q * 2 + 0], px0, a.x);
                ffma2(acc[q * 2 + 1], px0, a.y);
                ffma2(acc[q * 2 + 0], px1, b.x);
                ffma2(acc[q * 2 + 1], px1, b.y);
                ffma2(acc[q * 2 + 0], px2, cc.x);
                ffma2(acc[q * 2 + 1], px2, cc.y);
            }
        }
    }

    uint4* hp = (uint4*)(g_h16 + (size_t)n * FOUTC);
#pragma unroll
    for (int c = 0; c < 4; c++) {
        float r[8];
#pragma unroll
        for (int j = 0; j < 4; j++) {
            float lo, hi;
            upk2(acc[c * 4 + j], lo, hi);
            r[j * 2 + 0] = lo;
            r[j * 2 + 1] = hi;
        }
        uint w[4];
#pragma unroll
        for (int j = 0; j < 8; j++) {
            int o = c * 8 + j;
            float v = r[j] * sScale[o] + sShift[o];
            float sig = 1.f / (1.f + __expf(-v));
            r[j] = v * sig;
        }
#pragma unroll
        for (int j = 0; j < 4; j++) {
            __half2 h2 = __floats2half2_rn(r[j * 2], r[j * 2 + 1]);
            w[j] = *(uint*)&h2;
        }
        hp[c] = make_uint4(w[0], w[1], w[2], w[3]);
    }
}

// ---------------------------------------------------------------------------
// Stage 2 (HMMA + cp.async): D[128x32] += sum_k A_k[128x32] @ w2t_k[32x32]^T.
// Gather goes global->shared via cp.async (LDGSTS), 3-stage ring:
//   iter k: wait_group<1> (stage k done) -> ONE syncthreads (visibility +
//   WAR-safety for the issue below) -> issue stage k+2 (+ commit; empty
//   commits at the tail keep group counting sound) -> ldsm/mma stage k.
// Indices staged in smem from nbr_idx (coalesced, no global transpose).
// 4 lanes per h-row -> 8 lines/warp-inst gather. Swizzle verified.
// ---------------------------------------------------------------------------
#define C_THREADS 128
#define TILE_P    128
#define STG       3

__global__ void __launch_bounds__(C_THREADS) stage2_mma_kernel(
    const int*   __restrict__ nbr,
    const float* __restrict__ mlp_w,
    const float* __restrict__ mlp_b,
    const float* __restrict__ mg,
    const float* __restrict__ mbt,
    const float* __restrict__ mm,
    const float* __restrict__ mv,
    float* __restrict__ out)
{
    __shared__ __align__(1024) __half sA[STG][TILE_P * 32];  // 3 x 8 KB
    __shared__ __align__(1024) __half sB[STG][32 * 32];      // 3 x 2 KB
    __shared__ int   sIdx[TILE_P * KNBR];                    // 13.5 KB
    __shared__ float sPar[6][FOUTC];

    const int tid   = threadIdx.x;
    const int lane  = tid & 31;
    const int wid   = tid >> 5;
    const int wbase = wid * 32;
    const int base  = blockIdx.x * TILE_P;
    const int rsub  = tid >> 2;        // 0..31
    const int fc    = tid & 3;         // 16B chunk

    uint aAddr[STG], bAddr[STG];
#pragma unroll
    for (int s = 0; s < STG; s++) {
        aAddr[s] = s2u(sA[s]);
        bAddr[s] = s2u(sB[s]);
    }

    if (tid < FOUTC) {
        float s = rsqrtf(__ldg(mv + tid) + EPSV) * __ldg(mg + tid);
        sPar[0][tid] = s;
        sPar[1][tid] = __ldg(mbt + tid) - __ldg(mm + tid) * s;
        sPar[2][tid] = __ldg(mlp_w + tid);
        sPar[3][tid] = __ldg(mlp_w + 32 + tid);
        sPar[4][tid] = __ldg(mlp_w + 64 + tid);
        sPar[5][tid] = __ldg(mlp_b + tid);
    }
    for (int i = tid; i < TILE_P * KNBR; i += C_THREADS)
        sIdx[i] = nbr[(size_t)base * KNBR + i];
    __syncthreads();

    // ---- async gather of neighbor k into ring stage s
    auto issueK = [&](int k, int s) {
#pragma unroll
        for (int p = 0; p < 4; p++) {
            int row = 32 * p + rsub;
            int idx = sIdx[row * KNBR + k];
            cpa16(aAddr[s] + swoff(row, fc),
                  g_h16 + (size_t)idx * FOUTC + fc * 8);
        }
        cpa16(bAddr[s] + swoff(rsub, fc),
              g_w2t + (size_t)k * 1024 + tid * 8);
    };

    float acc[2][4][4];
#pragma unroll
    for (int mt = 0; mt < 2; mt++)
#pragma unroll
        for (int nt = 0; nt < 4; nt++)
#pragma unroll
            for (int c = 0; c < 4; c++) acc[mt][nt][c] = 0.f;

    issueK(0, 0); CP_COMMIT();
    issueK(1, 1); CP_COMMIT();

    for (int k = 0; k < KNBR; k++) {
        CP_WAIT1();          // stage k complete (own groups)
        __syncthreads();     // cross-thread visibility + prior compute done

        if (k + 2 < KNBR) issueK(k + 2, (k + 2) % STG);
        CP_COMMIT();         // always commit (empty at tail) for group counting

        const uint aB = aAddr[k % STG];
        const uint bB = bAddr[k % STG];

        uint a[2][2][4];
#pragma unroll
        for (int mt = 0; mt < 2; mt++)
#pragma unroll
            for (int kt = 0; kt < 2; kt++) {
                int r  = wbase + mt * 16 + (lane & 15);
                int ks = kt * 2 + (lane >> 4);
                ldsm4(aB + swoff(r, ks), a[mt][kt]);
            }
        uint b[2][2][4];
#pragma unroll
        for (int p = 0; p < 2; p++)
#pragma unroll
            for (int kt = 0; kt < 2; kt++) {
                int q  = lane >> 3;
                int nn = (p * 2 + (q >> 1)) * 8 + (lane & 7);
                int ks = kt * 2 + (q & 1);
                ldsm4(bB + swoff(nn, ks), b[p][kt]);
            }
#pragma unroll
        for (int mt = 0; mt < 2; mt++)
#pragma unroll
            for (int nt = 0; nt < 4; nt++) {
                int p = nt >> 1, h = (nt & 1) * 2;
#pragma unroll
                for (int kt = 0; kt < 2; kt++)
                    mma16816(acc[mt][nt], a[mt][kt], b[p][kt][h], b[p][kt][h + 1]);
            }
    }

    // ---- epilogue: fuse point branch, duplicated store
    const int cb = 2 * (lane & 3);
#pragma unroll
    for (int mt = 0; mt < 2; mt++) {
#pragma unroll
        for (int rr = 0; rr < 2; rr++) {
            int row = wbase + mt * 16 + rr * 8 + (lane >> 2);
            int n   = base + row;
            float4 z4 = __ldg((const float4*)g_z4 + n);
#pragma unroll
            for (int nt = 0; nt < 4; nt++) {
                int c0 = nt * 8 + cb;
                float r0 = acc[mt][nt][rr * 2 + 0];
                float r1 = acc[mt][nt][rr * 2 + 1];
                float zv0 = z4.x * sPar[2][c0] + z4.y * sPar[3][c0]
                          + z4.z * sPar[4][c0] + sPar[5][c0];
                zv0 = fmaxf(zv0 * sPar[0][c0] + sPar[1][c0], 0.f);
                float zv1 = z4.x * sPar[2][c0+1] + z4.y * sPar[3][c0+1]
                          + z4.z * sPar[4][c0+1] + sPar[5][c0+1];
                zv1 = fmaxf(zv1 * sPar[0][c0+1] + sPar[1][c0+1], 0.f);
                float2 st = make_float2(r0 + zv0, r1 + zv1);
                *(float2*)(out + (size_t)n * FOUTC + c0) = st;
                *(float2*)(out + (size_t)(NPTS + n) * FOUTC + c0) = st;
            }
        }
    }
}

// ---------------------------------------------------------------------------
extern "C" void kernel_launch(void* const* d_in, const int* in_sizes, int n_in,
                              void* d_out, int out_size)
{
    const float* x_feats   = (const float*)d_in[0];
    const float* z_feats   = (const float*)d_in[1];
    const int*   nbr_idx   = (const int*)  d_in[2];
    const float* w1        = (const float*)d_in[3];
    const float* bn1_gamma = (const float*)d_in[4];
    const float* bn1_beta  = (const float*)d_in[5];
    const float* bn1_mean  = (const float*)d_in[6];
    const float* bn1_var   = (const float*)d_in[7];
    const float* w2        = (const float*)d_in[8];
    const float* mlp_w     = (const float*)d_in[9];
    const float* mlp_b     = (const float*)d_in[10];
    const float* mlp_gamma = (const float*)d_in[11];
    const float* mlp_beta  = (const float*)d_in[12];
    const float* mlp_mean  = (const float*)d_in[13];
    const float* mlp_var   = (const float*)d_in[14];
    float* out = (float*)d_out;

    prep_kernel<<<NPTS / 256, 256>>>(x_feats, z_feats, w2);

    stage1_kernel<<<NPTS / A_THREADS, A_THREADS>>>(
        nbr_idx, w1, bn1_gamma, bn1_beta, bn1_mean, bn1_var);

    stage2_mma_kernel<<<NPTS / TILE_P, C_THREADS>>>(
        nbr_idx, mlp_w, mlp_b, mlp_gamma, mlp_beta, mlp_mean, mlp_var, out);
}